// round 3
// baseline (speedup 1.0000x reference)
#include <cuda_runtime.h>
#include <cuda_bf16.h>
#include <math.h>

// ---------------------------------------------------------------------------
// GPT-2 block, fp32 baseline.
// B=2, S=2048, D=1024, H=16, dh=64, INNER=4096
// ---------------------------------------------------------------------------

#define BATCH   2
#define SEQ     2048
#define DMODEL  1024
#define NHEADS  16
#define HDIM    64
#define INNER   4096
#define ROWS    (BATCH * SEQ)          // 4096
#define EPS     1e-5f

// ------------------------- scratch (static device mem) ---------------------
__device__ float g_x   [ROWS * DMODEL];       // ln1 output
__device__ float g_qkv [ROWS * 3 * DMODEL];   // fused qkv
__device__ float g_attn[ROWS * DMODEL];       // attention output (pre-proj)
__device__ float g_h2  [ROWS * DMODEL];       // attn proj + residual
__device__ float g_y   [ROWS * DMODEL];       // ln2 output
__device__ float g_fc  [ROWS * INNER];        // gelu(fc) output

// ------------------------------- LayerNorm ---------------------------------
__global__ void __launch_bounds__(256) ln_kernel(
    const float* __restrict__ in, const float* __restrict__ gamma,
    const float* __restrict__ beta, float* __restrict__ out)
{
    __shared__ float red[16];
    const int row = blockIdx.x;
    const int tid = threadIdx.x;
    const float* x = in + (size_t)row * DMODEL;

    float4 v = *(const float4*)(x + tid * 4);
    float s = v.x + v.y + v.z + v.w;
    float q = v.x * v.x + v.y * v.y + v.z * v.z + v.w * v.w;
    #pragma unroll
    for (int off = 16; off; off >>= 1) {
        s += __shfl_xor_sync(0xffffffffu, s, off);
        q += __shfl_xor_sync(0xffffffffu, q, off);
    }
    const int w = tid >> 5;
    if ((tid & 31) == 0) { red[w] = s; red[8 + w] = q; }
    __syncthreads();
    float st = 0.f, qt = 0.f;
    #pragma unroll
    for (int i = 0; i < 8; i++) { st += red[i]; qt += red[8 + i]; }

    const float mu  = st * (1.0f / DMODEL);
    const float var = qt * (1.0f / DMODEL) - mu * mu;
    const float inv = rsqrtf(var + EPS);

    float4 g = *(const float4*)(gamma + tid * 4);
    float4 b = *(const float4*)(beta  + tid * 4);
    float4 o;
    o.x = (v.x - mu) * inv * g.x + b.x;
    o.y = (v.y - mu) * inv * g.y + b.y;
    o.z = (v.z - mu) * inv * g.z + b.z;
    o.w = (v.w - mu) * inv * g.w + b.w;
    *(float4*)(out + (size_t)row * DMODEL + tid * 4) = o;
}

// --------------------------------- SGEMM -----------------------------------
// C[M,N] = A[M,K] @ B[K,N] + bias  (+ residual | gelu)
// 128x128 tile, BK=8, 8x8 per thread, 256 threads. All dims % 128 == 0.
#define EPI_BIAS  0
#define EPI_RES   1
#define EPI_GELU  2

__device__ __forceinline__ float gelu_exact(float x) {
    return 0.5f * x * (1.0f + erff(x * 0.70710678118654752f));
}

template <int EPI>
__global__ void __launch_bounds__(256) sgemm_kernel(
    const float* __restrict__ A, const float* __restrict__ Bm,
    const float* __restrict__ bias, const float* __restrict__ res,
    float* __restrict__ C, int M, int N, int K)
{
    __shared__ float As[8][128];
    __shared__ float Bs[8][128];

    const int tid  = threadIdx.x;
    const int brow = blockIdx.y;
    const int bcol = blockIdx.x;
    const int tr   = tid >> 4;       // 0..15
    const int tc   = tid & 15;       // 0..15

    const int arow  = tid >> 1;           // 0..127
    const int ak    = (tid & 1) * 4;      // 0 or 4
    const int bkr   = tid >> 5;           // 0..7
    const int bcol4 = (tid & 31) * 4;     // 0..124

    const float* Aptr = A  + (size_t)(brow * 128 + arow) * K + ak;
    const float* Bptr = Bm + (size_t)bkr * N + bcol * 128 + bcol4;

    float acc[8][8];
    #pragma unroll
    for (int i = 0; i < 8; i++)
        #pragma unroll
        for (int j = 0; j < 8; j++) acc[i][j] = 0.f;

    for (int kt = 0; kt < K; kt += 8) {
        float4 a4 = *(const float4*)(Aptr + kt);
        As[ak + 0][arow] = a4.x;
        As[ak + 1][arow] = a4.y;
        As[ak + 2][arow] = a4.z;
        As[ak + 3][arow] = a4.w;
        float4 b4 = *(const float4*)(Bptr + (size_t)kt * N);
        *(float4*)&Bs[bkr][bcol4] = b4;
        __syncthreads();

        #pragma unroll
        for (int k = 0; k < 8; k++) {
            float4 a0 = *(const float4*)&As[k][tr * 8];
            float4 a1 = *(const float4*)&As[k][tr * 8 + 4];
            float4 b0 = *(const float4*)&Bs[k][tc * 8];
            float4 b1 = *(const float4*)&Bs[k][tc * 8 + 4];
            float a[8] = {a0.x, a0.y, a0.z, a0.w, a1.x, a1.y, a1.z, a1.w};
            float b[8] = {b0.x, b0.y, b0.z, b0.w, b1.x, b1.y, b1.z, b1.w};
            #pragma unroll
            for (int i = 0; i < 8; i++)
                #pragma unroll
                for (int j = 0; j < 8; j++)
                    acc[i][j] = fmaf(a[i], b[j], acc[i][j]);
        }
        __syncthreads();
    }

    // epilogue
    #pragma unroll
    for (int i = 0; i < 8; i++) {
        const size_t row = brow * 128 + tr * 8 + i;
        #pragma unroll
        for (int j = 0; j < 8; j += 4) {
            const size_t col = bcol * 128 + tc * 8 + j;
            float4 bv = *(const float4*)(bias + col);
            float4 o;
            o.x = acc[i][j + 0] + bv.x;
            o.y = acc[i][j + 1] + bv.y;
            o.z = acc[i][j + 2] + bv.z;
            o.w = acc[i][j + 3] + bv.w;
            if (EPI == EPI_RES) {
                float4 rv = *(const float4*)(res + row * N + col);
                o.x += rv.x; o.y += rv.y; o.z += rv.z; o.w += rv.w;
            }
            if (EPI == EPI_GELU) {
                o.x = gelu_exact(o.x); o.y = gelu_exact(o.y);
                o.z = gelu_exact(o.z); o.w = gelu_exact(o.w);
            }
            *(float4*)(C + row * N + col) = o;
        }
    }
}

// ----------------------------- Flash attention ------------------------------
// grid = (SEQ/64, BATCH*NHEADS), 256 threads. 64q x 64k tiles, dh = 64.
// Thread (ty,tx) owns a 4x4 micro-tile of the 64x64 score / output tile.
#define ATTN_SMEM_FLOATS (64 * 64 + 64 * 65 + 64 * 65)   // Qs, Ks(pad), Vs(pad)

__global__ void __launch_bounds__(256) attn_kernel(
    const float* __restrict__ qkv, float* __restrict__ out)
{
    extern __shared__ float sm[];
    float* Qs = sm;               // [64][64]
    float* Ks = Qs + 64 * 64;     // [64][65]
    float* Vs = Ks + 64 * 65;     // [64][65]
    float* Ps = Ks;               // P reuses K's smem

    const int qt = blockIdx.x;
    const int b  = blockIdx.y >> 4;
    const int h  = blockIdx.y & 15;
    const int tid = threadIdx.x;
    const int ty = tid >> 4, tx = tid & 15;

    const size_t rowbase = (size_t)b * SEQ * (3 * DMODEL);
    const float* Qg = qkv + rowbase + (size_t)qt * 64 * (3 * DMODEL) + h * HDIM;

    // load Q tile [64][64]
    for (int idx = tid; idx < 64 * 16; idx += 256) {
        const int r = idx >> 4, c = (idx & 15) << 2;
        float4 v = *(const float4*)(Qg + (size_t)r * (3 * DMODEL) + c);
        float* p = Qs + r * 64 + c;
        p[0] = v.x; p[1] = v.y; p[2] = v.z; p[3] = v.w;
    }

    float m_i[4], l_i[4], o[4][4];
    #pragma unroll
    for (int i = 0; i < 4; i++) {
        m_i[i] = -1e30f; l_i[i] = 0.f;
        #pragma unroll
        for (int j = 0; j < 4; j++) o[i][j] = 0.f;
    }

    for (int jt = 0; jt <= qt; jt++) {
        __syncthreads();   // prior-iter P/V reads (and first-iter Q load) done
        const float* Kg = qkv + rowbase + (size_t)jt * 64 * (3 * DMODEL) + DMODEL + h * HDIM;
        const float* Vg = Kg + DMODEL;
        for (int idx = tid; idx < 64 * 16; idx += 256) {
            const int r = idx >> 4, c = (idx & 15) << 2;
            float4 kv = *(const float4*)(Kg + (size_t)r * (3 * DMODEL) + c);
            float* kp = Ks + r * 65 + c;
            kp[0] = kv.x; kp[1] = kv.y; kp[2] = kv.z; kp[3] = kv.w;
            float4 vv = *(const float4*)(Vg + (size_t)r * (3 * DMODEL) + c);
            float* vp = Vs + r * 65 + c;
            vp[0] = vv.x; vp[1] = vv.y; vp[2] = vv.z; vp[3] = vv.w;
        }
        __syncthreads();

        // S = Q @ K^T
        float s[4][4];
        #pragma unroll
        for (int i = 0; i < 4; i++)
            #pragma unroll
            for (int j = 0; j < 4; j++) s[i][j] = 0.f;
        #pragma unroll 4
        for (int d = 0; d < 64; d++) {
            float a[4], bb[4];
            #pragma unroll
            for (int i = 0; i < 4; i++) a[i]  = Qs[(4 * ty + i) * 64 + d];
            #pragma unroll
            for (int j = 0; j < 4; j++) bb[j] = Ks[(4 * tx + j) * 65 + d];
            #pragma unroll
            for (int i = 0; i < 4; i++)
                #pragma unroll
                for (int j = 0; j < 4; j++)
                    s[i][j] = fmaf(a[i], bb[j], s[i][j]);
        }

        // scale + causal mask
        #pragma unroll
        for (int i = 0; i < 4; i++) {
            const int qrow = qt * 64 + 4 * ty + i;
            #pragma unroll
            for (int j = 0; j < 4; j++) {
                const int kcol = jt * 64 + 4 * tx + j;
                s[i][j] = (kcol <= qrow) ? s[i][j] * 0.125f : -1e30f;
            }
        }

        // online softmax (row spread over 16 lanes: width-16 shuffles)
        #pragma unroll
        for (int i = 0; i < 4; i++) {
            float mx = fmaxf(fmaxf(s[i][0], s[i][1]), fmaxf(s[i][2], s[i][3]));
            #pragma unroll
            for (int off = 8; off; off >>= 1)
                mx = fmaxf(mx, __shfl_xor_sync(0xffffffffu, mx, off, 16));
            const float m_new = fmaxf(m_i[i], mx);
            const float alpha = __expf(m_i[i] - m_new);
            float rsum = 0.f;
            #pragma unroll
            for (int j = 0; j < 4; j++) {
                s[i][j] = __expf(s[i][j] - m_new);
                rsum += s[i][j];
            }
            #pragma unroll
            for (int off = 8; off; off >>= 1)
                rsum += __shfl_xor_sync(0xffffffffu, rsum, off, 16);
            l_i[i] = l_i[i] * alpha + rsum;
            m_i[i] = m_new;
            #pragma unroll
            for (int j = 0; j < 4; j++) o[i][j] *= alpha;
        }

        __syncthreads();   // everyone done reading Ks before overwriting with P
        #pragma unroll
        for (int i = 0; i < 4; i++)
            #pragma unroll
            for (int j = 0; j < 4; j++)
                Ps[(4 * ty + i) * 65 + 4 * tx + j] = s[i][j];
        __syncthreads();

        // O += P @ V
        #pragma unroll 4
        for (int j = 0; j < 64; j++) {
            float p[4], v[4];
            #pragma unroll
            for (int i = 0; i < 4; i++) p[i] = Ps[(4 * ty + i) * 65 + j];
            #pragma unroll
            for (int c = 0; c < 4; c++) v[c] = Vs[j * 65 + 4 * tx + c];
            #pragma unroll
            for (int i = 0; i < 4; i++)
                #pragma unroll
                for (int c = 0; c < 4; c++)
                    o[i][c] = fmaf(p[i], v[c], o[i][c]);
        }
    }

    // write normalized output
    float* Og = out + ((size_t)b * SEQ + (size_t)qt * 64) * DMODEL + h * HDIM;
    #pragma unroll
    for (int i = 0; i < 4; i++) {
        const float inv = 1.0f / l_i[i];
        const int r = 4 * ty + i;
        #pragma unroll
        for (int c = 0; c < 4; c++)
            Og[(size_t)r * DMODEL + 4 * tx + c] = o[i][c] * inv;
    }
}

// ------------------------------- launcher -----------------------------------
extern "C" void kernel_launch(void* const* d_in, const int* in_sizes, int n_in,
                              void* d_out, int out_size)
{
    const float* hidden = (const float*)d_in[0];
    const float* w_qkv  = (const float*)d_in[1];
    const float* b_qkv  = (const float*)d_in[2];
    const float* g1     = (const float*)d_in[3];
    const float* be1    = (const float*)d_in[4];
    const float* w_proj = (const float*)d_in[5];
    const float* b_proj = (const float*)d_in[6];
    const float* g2     = (const float*)d_in[7];
    const float* be2    = (const float*)d_in[8];
    const float* w_fc   = (const float*)d_in[9];
    const float* b_fc   = (const float*)d_in[10];
    const float* w_mlp  = (const float*)d_in[11];
    const float* b_mlp  = (const float*)d_in[12];
    float* out = (float*)d_out;

    float *x, *qkv, *attn, *h2, *y, *fc;
    cudaGetSymbolAddress((void**)&x,    g_x);
    cudaGetSymbolAddress((void**)&qkv,  g_qkv);
    cudaGetSymbolAddress((void**)&attn, g_attn);
    cudaGetSymbolAddress((void**)&h2,   g_h2);
    cudaGetSymbolAddress((void**)&y,    g_y);
    cudaGetSymbolAddress((void**)&fc,   g_fc);

    const int attn_smem = ATTN_SMEM_FLOATS * (int)sizeof(float);  // 49664 B
    cudaFuncSetAttribute(attn_kernel,
                         cudaFuncAttributeMaxDynamicSharedMemorySize, attn_smem);

    // 1. LN1
    ln_kernel<<<ROWS, 256>>>(hidden, g1, be1, x);
    // 2. QKV = x @ w_qkv + b_qkv      [4096,1024]x[1024,3072]
    {
        dim3 grid(3 * DMODEL / 128, ROWS / 128);
        sgemm_kernel<EPI_BIAS><<<grid, 256>>>(x, w_qkv, b_qkv, nullptr, qkv,
                                              ROWS, 3 * DMODEL, DMODEL);
    }
    // 3. attention
    {
        dim3 grid(SEQ / 64, BATCH * NHEADS);
        attn_kernel<<<grid, 256, attn_smem>>>(qkv, attn);
    }
    // 4. h2 = attn @ w_proj + b_proj + hidden
    {
        dim3 grid(DMODEL / 128, ROWS / 128);
        sgemm_kernel<EPI_RES><<<grid, 256>>>(attn, w_proj, b_proj, hidden, h2,
                                             ROWS, DMODEL, DMODEL);
    }
    // 5. LN2
    ln_kernel<<<ROWS, 256>>>(h2, g2, be2, y);
    // 6. fc = gelu(y @ w_fc + b_fc)   [4096,1024]x[1024,4096]
    {
        dim3 grid(INNER / 128, ROWS / 128);
        sgemm_kernel<EPI_GELU><<<grid, 256>>>(y, w_fc, b_fc, nullptr, fc,
                                              ROWS, INNER, DMODEL);
    }
    // 7. out = fc @ w_mlp + b_mlp + h2
    {
        dim3 grid(DMODEL / 128, ROWS / 128);
        sgemm_kernel<EPI_RES><<<grid, 256>>>(fc, w_mlp, b_mlp, h2, out,
                                             ROWS, DMODEL, INNER);
    }
}

// round 5
// speedup vs baseline: 2.1050x; 2.1050x over previous
#include <cuda_runtime.h>
#include <cuda_bf16.h>
#include <math.h>
#include <stdint.h>

// ---------------------------------------------------------------------------
// GPT-2 block. GEMMs via warp-level mma.sync tf32 (sm_80+ path; the harness
// targets plain sm_100, so tcgen05/'a'-features are unavailable).
// B=2, S=2048, D=1024, H=16, dh=64, INNER=4096
// ---------------------------------------------------------------------------

#define BATCH   2
#define SEQ     2048
#define DMODEL  1024
#define NHEADS  16
#define HDIM    64
#define INNER   4096
#define ROWS    (BATCH * SEQ)          // 4096
#define EPS     1e-5f

// ------------------------- scratch (static device mem) ---------------------
__device__ float g_x   [ROWS * DMODEL];       // ln1 output (tf32-rounded)
__device__ float g_qkv [ROWS * 3 * DMODEL];   // fused qkv
__device__ float g_attn[ROWS * DMODEL];       // attention output (tf32-rounded)
__device__ float g_h2  [ROWS * DMODEL];       // attn proj + residual
__device__ float g_y   [ROWS * DMODEL];       // ln2 output (tf32-rounded)
__device__ float g_fc  [ROWS * INNER];        // gelu(fc) (tf32-rounded)
__device__ float g_wT  [12 * 1024 * 1024];    // transposed weights (tf32-rounded)
#define WT_QKV_OFF  0                              // [3072,1024]
#define WT_PROJ_OFF (3072 * 1024)                  // [1024,1024]
#define WT_FC_OFF   (WT_PROJ_OFF + 1024 * 1024)    // [4096,1024]
#define WT_MLP_OFF  (WT_FC_OFF + 4096 * 1024)      // [1024,4096]

// ------------------------------ small helpers -------------------------------
__device__ __forceinline__ float tf32r(float x) {
    unsigned r;
    asm("cvt.rna.tf32.f32 %0, %1;" : "=r"(r) : "f"(x));
    return __uint_as_float(r);
}

__device__ __forceinline__ float gelu_exact(float x) {
    return 0.5f * x * (1.0f + erff(x * 0.70710678118654752f));
}

__device__ __forceinline__ uint32_t smem_u32(const void* p) {
    uint32_t a;
    asm("{ .reg .u64 t; cvta.to.shared.u64 t, %1; cvt.u32.u64 %0, t; }"
        : "=r"(a) : "l"(p));
    return a;
}

__device__ __forceinline__ void cpa16(uint32_t dst, const float* src) {
    asm volatile("cp.async.cg.shared.global [%0], [%1], 16;" :: "r"(dst), "l"(src));
}

__device__ __forceinline__ void mma_tf32(
    float& c0, float& c1, float& c2, float& c3,
    uint32_t a0, uint32_t a1, uint32_t a2, uint32_t a3,
    uint32_t b0, uint32_t b1)
{
    asm volatile(
        "mma.sync.aligned.m16n8k8.row.col.f32.tf32.tf32.f32 "
        "{%0,%1,%2,%3}, {%4,%5,%6,%7}, {%8,%9}, {%0,%1,%2,%3};"
        : "+f"(c0), "+f"(c1), "+f"(c2), "+f"(c3)
        : "r"(a0), "r"(a1), "r"(a2), "r"(a3), "r"(b0), "r"(b1));
}

// ------------------------------- LayerNorm ---------------------------------
__global__ void __launch_bounds__(256) ln_kernel(
    const float* __restrict__ in, const float* __restrict__ gamma,
    const float* __restrict__ beta, float* __restrict__ out)
{
    __shared__ float red[16];
    const int row = blockIdx.x;
    const int tid = threadIdx.x;
    const float* x = in + (size_t)row * DMODEL;

    float4 v = *(const float4*)(x + tid * 4);
    float s = v.x + v.y + v.z + v.w;
    float q = v.x * v.x + v.y * v.y + v.z * v.z + v.w * v.w;
    #pragma unroll
    for (int off = 16; off; off >>= 1) {
        s += __shfl_xor_sync(0xffffffffu, s, off);
        q += __shfl_xor_sync(0xffffffffu, q, off);
    }
    const int w = tid >> 5;
    if ((tid & 31) == 0) { red[w] = s; red[8 + w] = q; }
    __syncthreads();
    float st = 0.f, qt = 0.f;
    #pragma unroll
    for (int i = 0; i < 8; i++) { st += red[i]; qt += red[8 + i]; }

    const float mu  = st * (1.0f / DMODEL);
    const float var = qt * (1.0f / DMODEL) - mu * mu;
    const float inv = rsqrtf(var + EPS);

    float4 g = *(const float4*)(gamma + tid * 4);
    float4 b = *(const float4*)(beta  + tid * 4);
    float4 o;
    o.x = tf32r((v.x - mu) * inv * g.x + b.x);
    o.y = tf32r((v.y - mu) * inv * g.y + b.y);
    o.z = tf32r((v.z - mu) * inv * g.z + b.z);
    o.w = tf32r((v.w - mu) * inv * g.w + b.w);
    *(float4*)(out + (size_t)row * DMODEL + tid * 4) = o;
}

// ----------------------- weight transpose (+tf32 round) --------------------
// in: [K,N] row-major -> out: [N,K] row-major
__global__ void __launch_bounds__(256) transpose_tf32_kernel(
    const float* __restrict__ in, float* __restrict__ out, int K, int N)
{
    __shared__ float t[32][33];
    const int n0 = blockIdx.x * 32;
    const int k0 = blockIdx.y * 32;
    const int tx = threadIdx.x & 31;
    const int ty = threadIdx.x >> 5;
    #pragma unroll
    for (int i = 0; i < 32; i += 8)
        t[ty + i][tx] = in[(size_t)(k0 + ty + i) * N + n0 + tx];
    __syncthreads();
    #pragma unroll
    for (int i = 0; i < 32; i += 8)
        out[(size_t)(n0 + ty + i) * K + k0 + tx] = tf32r(t[tx][ty + i]);
}

// ------------------------------ tf32 MMA GEMM -------------------------------
// C[M,N] = A[M,K] @ Bt[N,K]^T (+bias, +res | gelu). M,N % 128 == 0, K % 32 == 0.
// 128x128 CTA tile, BK=32, 8 warps (2Mx4N), warp tile 64x32, m16n8k8 tf32.
#define EPI_BIAS  0
#define EPI_RES   1
#define EPI_GELU  2

#define BK       32
#define SPITCH   36                        // words per smem row (16B-aligned, conflict-free)
#define STAGE_FLOATS (2 * 128 * SPITCH)    // A tile + B tile
#define GSMEM_DYN (2 * STAGE_FLOATS * 4)   // double buffer: 73728 B

template <int EPI>
__global__ void __launch_bounds__(256, 2) tc_gemm_kernel(
    const float* __restrict__ A, const float* __restrict__ Bt,
    const float* __restrict__ bias, const float* __restrict__ res,
    float* __restrict__ C, int M, int N, int K)
{
    extern __shared__ float smf[];

    const int tid   = threadIdx.x;
    const int wid   = tid >> 5;
    const int lane  = tid & 31;
    const int gi    = lane >> 2;       // 0..7
    const int tig   = lane & 3;        // 0..3
    const int warpM = wid >> 2;        // 0..1
    const int warpN = wid & 3;         // 0..3

    const int mrow0 = blockIdx.y * 128;
    const int ncol0 = blockIdx.x * 128;

    const float* Abase = A  + (size_t)mrow0 * K;
    const float* Bbase = Bt + (size_t)ncol0 * K;

    const uint32_t smem_base = smem_u32(smf);

    float acc[4][4][4];
    #pragma unroll
    for (int i = 0; i < 4; i++)
        #pragma unroll
        for (int j = 0; j < 4; j++)
            #pragma unroll
            for (int q = 0; q < 4; q++) acc[i][j][q] = 0.f;

    // per-thread gmem->smem slice: 4 x 16B for A, 4 x 16B for B per stage
    const int NC = K / BK;

    auto load_stage = [&](int c) {
        const int s = c & 1;
        const uint32_t a_st = smem_base + s * STAGE_FLOATS * 4;
        const uint32_t b_st = a_st + 128 * SPITCH * 4;
        const int kof = c * BK;
        #pragma unroll
        for (int i = 0; i < 4; i++) {
            const int lin = tid + i * 256;      // 0..1023
            const int r   = lin >> 3;           // 0..127
            const int cc  = lin & 7;            // 0..7 (x4 floats)
            const uint32_t off = (uint32_t)(r * SPITCH + cc * 4) * 4;
            cpa16(a_st + off, Abase + (size_t)r * K + kof + cc * 4);
            cpa16(b_st + off, Bbase + (size_t)r * K + kof + cc * 4);
        }
        asm volatile("cp.async.commit_group;" ::: "memory");
    };

    load_stage(0);

    for (int c = 0; c < NC; c++) {
        if (c + 1 < NC) {
            load_stage(c + 1);
            asm volatile("cp.async.wait_group 1;" ::: "memory");
        } else {
            asm volatile("cp.async.wait_group 0;" ::: "memory");
        }
        __syncthreads();

        const float* As = smf + (c & 1) * STAGE_FLOATS;
        const float* Bs = As + 128 * SPITCH;
        const float* Aw = As + (warpM * 64 + gi) * SPITCH + tig;
        const float* Bw = Bs + (warpN * 32 + gi) * SPITCH + tig;

        #pragma unroll
        for (int ks = 0; ks < BK; ks += 8) {
            uint32_t af[4][4], bf[4][2];
            #pragma unroll
            for (int im = 0; im < 4; im++) {
                const float* p = Aw + im * 16 * SPITCH + ks;
                af[im][0] = __float_as_uint(p[0]);
                af[im][1] = __float_as_uint(p[8 * SPITCH]);
                af[im][2] = __float_as_uint(p[4]);
                af[im][3] = __float_as_uint(p[8 * SPITCH + 4]);
            }
            #pragma unroll
            for (int jn = 0; jn < 4; jn++) {
                const float* p = Bw + jn * 8 * SPITCH + ks;
                bf[jn][0] = __float_as_uint(p[0]);
                bf[jn][1] = __float_as_uint(p[4]);
            }
            #pragma unroll
            for (int im = 0; im < 4; im++)
                #pragma unroll
                for (int jn = 0; jn < 4; jn++)
                    mma_tf32(acc[im][jn][0], acc[im][jn][1],
                             acc[im][jn][2], acc[im][jn][3],
                             af[im][0], af[im][1], af[im][2], af[im][3],
                             bf[jn][0], bf[jn][1]);
        }
        __syncthreads();
    }

    // ---- epilogue: C fragment (row=gi|gi+8, col=2*tig|2*tig+1) -------------
    #pragma unroll
    for (int im = 0; im < 4; im++) {
        const int r0 = mrow0 + warpM * 64 + im * 16 + gi;
        #pragma unroll
        for (int half = 0; half < 2; half++) {
            const size_t row = (size_t)(r0 + half * 8);
            float* Crow = C + row * N;
            const float* Rrow = (EPI == EPI_RES) ? (res + row * N) : nullptr;
            #pragma unroll
            for (int jn = 0; jn < 4; jn++) {
                const int col = ncol0 + warpN * 32 + jn * 8 + tig * 2;
                float2 o;
                o.x = acc[im][jn][half * 2 + 0];
                o.y = acc[im][jn][half * 2 + 1];
                float2 bv = *(const float2*)(bias + col);
                o.x += bv.x; o.y += bv.y;
                if (EPI == EPI_RES) {
                    float2 rv = *(const float2*)(Rrow + col);
                    o.x += rv.x; o.y += rv.y;
                }
                if (EPI == EPI_GELU) {
                    o.x = tf32r(gelu_exact(o.x));
                    o.y = tf32r(gelu_exact(o.y));
                }
                *(float2*)(Crow + col) = o;
            }
        }
    }
}

// ----------------------------- Flash attention ------------------------------
#define ATTN_SMEM_FLOATS (64 * 64 + 64 * 65 + 64 * 65)

__global__ void __launch_bounds__(256) attn_kernel(
    const float* __restrict__ qkv, float* __restrict__ out)
{
    extern __shared__ float sm[];
    float* Qs = sm;
    float* Ks = Qs + 64 * 64;
    float* Vs = Ks + 64 * 65;
    float* Ps = Ks;

    const int qt = blockIdx.x;
    const int b  = blockIdx.y >> 4;
    const int h  = blockIdx.y & 15;
    const int tid = threadIdx.x;
    const int ty = tid >> 4, tx = tid & 15;

    const size_t rowbase = (size_t)b * SEQ * (3 * DMODEL);
    const float* Qg = qkv + rowbase + (size_t)qt * 64 * (3 * DMODEL) + h * HDIM;

    for (int idx = tid; idx < 64 * 16; idx += 256) {
        const int r = idx >> 4, c = (idx & 15) << 2;
        float4 v = *(const float4*)(Qg + (size_t)r * (3 * DMODEL) + c);
        float* p = Qs + r * 64 + c;
        p[0] = v.x; p[1] = v.y; p[2] = v.z; p[3] = v.w;
    }

    float m_i[4], l_i[4], o[4][4];
    #pragma unroll
    for (int i = 0; i < 4; i++) {
        m_i[i] = -1e30f; l_i[i] = 0.f;
        #pragma unroll
        for (int j = 0; j < 4; j++) o[i][j] = 0.f;
    }

    for (int jt = 0; jt <= qt; jt++) {
        __syncthreads();
        const float* Kg = qkv + rowbase + (size_t)jt * 64 * (3 * DMODEL) + DMODEL + h * HDIM;
        const float* Vg = Kg + DMODEL;
        for (int idx = tid; idx < 64 * 16; idx += 256) {
            const int r = idx >> 4, c = (idx & 15) << 2;
            float4 kv = *(const float4*)(Kg + (size_t)r * (3 * DMODEL) + c);
            float* kp = Ks + r * 65 + c;
            kp[0] = kv.x; kp[1] = kv.y; kp[2] = kv.z; kp[3] = kv.w;
            float4 vv = *(const float4*)(Vg + (size_t)r * (3 * DMODEL) + c);
            float* vp = Vs + r * 65 + c;
            vp[0] = vv.x; vp[1] = vv.y; vp[2] = vv.z; vp[3] = vv.w;
        }
        __syncthreads();

        float s[4][4];
        #pragma unroll
        for (int i = 0; i < 4; i++)
            #pragma unroll
            for (int j = 0; j < 4; j++) s[i][j] = 0.f;
        #pragma unroll 4
        for (int d = 0; d < 64; d++) {
            float a[4], bb[4];
            #pragma unroll
            for (int i = 0; i < 4; i++) a[i]  = Qs[(4 * ty + i) * 64 + d];
            #pragma unroll
            for (int j = 0; j < 4; j++) bb[j] = Ks[(4 * tx + j) * 65 + d];
            #pragma unroll
            for (int i = 0; i < 4; i++)
                #pragma unroll
                for (int j = 0; j < 4; j++)
                    s[i][j] = fmaf(a[i], bb[j], s[i][j]);
        }

        #pragma unroll
        for (int i = 0; i < 4; i++) {
            const int qrow = qt * 64 + 4 * ty + i;
            #pragma unroll
            for (int j = 0; j < 4; j++) {
                const int kcol = jt * 64 + 4 * tx + j;
                s[i][j] = (kcol <= qrow) ? s[i][j] * 0.125f : -1e30f;
            }
        }

        #pragma unroll
        for (int i = 0; i < 4; i++) {
            float mx = fmaxf(fmaxf(s[i][0], s[i][1]), fmaxf(s[i][2], s[i][3]));
            #pragma unroll
            for (int off = 8; off; off >>= 1)
                mx = fmaxf(mx, __shfl_xor_sync(0xffffffffu, mx, off, 16));
            const float m_new = fmaxf(m_i[i], mx);
            const float alpha = __expf(m_i[i] - m_new);
            float rsum = 0.f;
            #pragma unroll
            for (int j = 0; j < 4; j++) {
                s[i][j] = __expf(s[i][j] - m_new);
                rsum += s[i][j];
            }
            #pragma unroll
            for (int off = 8; off; off >>= 1)
                rsum += __shfl_xor_sync(0xffffffffu, rsum, off, 16);
            l_i[i] = l_i[i] * alpha + rsum;
            m_i[i] = m_new;
            #pragma unroll
            for (int j = 0; j < 4; j++) o[i][j] *= alpha;
        }

        __syncthreads();
        #pragma unroll
        for (int i = 0; i < 4; i++)
            #pragma unroll
            for (int j = 0; j < 4; j++)
                Ps[(4 * ty + i) * 65 + 4 * tx + j] = s[i][j];
        __syncthreads();

        #pragma unroll 4
        for (int j = 0; j < 64; j++) {
            float p[4], v[4];
            #pragma unroll
            for (int i = 0; i < 4; i++) p[i] = Ps[(4 * ty + i) * 65 + j];
            #pragma unroll
            for (int c = 0; c < 4; c++) v[c] = Vs[j * 65 + 4 * tx + c];
            #pragma unroll
            for (int i = 0; i < 4; i++)
                #pragma unroll
                for (int c = 0; c < 4; c++)
                    o[i][c] = fmaf(p[i], v[c], o[i][c]);
        }
    }

    float* Og = out + ((size_t)b * SEQ + (size_t)qt * 64) * DMODEL + h * HDIM;
    #pragma unroll
    for (int i = 0; i < 4; i++) {
        const float inv = 1.0f / l_i[i];
        const int r = 4 * ty + i;
        #pragma unroll
        for (int c = 0; c < 4; c++)
            Og[(size_t)r * DMODEL + 4 * tx + c] = tf32r(o[i][c] * inv);
    }
}

// ------------------------------- launcher -----------------------------------
extern "C" void kernel_launch(void* const* d_in, const int* in_sizes, int n_in,
                              void* d_out, int out_size)
{
    const float* hidden = (const float*)d_in[0];
    const float* w_qkv  = (const float*)d_in[1];
    const float* b_qkv  = (const float*)d_in[2];
    const float* g1     = (const float*)d_in[3];
    const float* be1    = (const float*)d_in[4];
    const float* w_proj = (const float*)d_in[5];
    const float* b_proj = (const float*)d_in[6];
    const float* g2     = (const float*)d_in[7];
    const float* be2    = (const float*)d_in[8];
    const float* w_fc   = (const float*)d_in[9];
    const float* b_fc   = (const float*)d_in[10];
    const float* w_mlp  = (const float*)d_in[11];
    const float* b_mlp  = (const float*)d_in[12];
    float* out = (float*)d_out;

    float *x, *qkv, *attn, *h2, *y, *fc, *wT;
    cudaGetSymbolAddress((void**)&x,    g_x);
    cudaGetSymbolAddress((void**)&qkv,  g_qkv);
    cudaGetSymbolAddress((void**)&attn, g_attn);
    cudaGetSymbolAddress((void**)&h2,   g_h2);
    cudaGetSymbolAddress((void**)&y,    g_y);
    cudaGetSymbolAddress((void**)&fc,   g_fc);
    cudaGetSymbolAddress((void**)&wT,   g_wT);

    float* wT_qkv  = wT + WT_QKV_OFF;
    float* wT_proj = wT + WT_PROJ_OFF;
    float* wT_fc   = wT + WT_FC_OFF;
    float* wT_mlp  = wT + WT_MLP_OFF;

    const int attn_smem = ATTN_SMEM_FLOATS * (int)sizeof(float);
    cudaFuncSetAttribute(attn_kernel,
                         cudaFuncAttributeMaxDynamicSharedMemorySize, attn_smem);
    cudaFuncSetAttribute(tc_gemm_kernel<EPI_BIAS>,
                         cudaFuncAttributeMaxDynamicSharedMemorySize, GSMEM_DYN);
    cudaFuncSetAttribute(tc_gemm_kernel<EPI_RES>,
                         cudaFuncAttributeMaxDynamicSharedMemorySize, GSMEM_DYN);
    cudaFuncSetAttribute(tc_gemm_kernel<EPI_GELU>,
                         cudaFuncAttributeMaxDynamicSharedMemorySize, GSMEM_DYN);

    // 0. transpose + tf32-round weights
    transpose_tf32_kernel<<<dim3(3 * DMODEL / 32, DMODEL / 32), 256>>>(w_qkv,  wT_qkv,  DMODEL, 3 * DMODEL);
    transpose_tf32_kernel<<<dim3(DMODEL / 32,     DMODEL / 32), 256>>>(w_proj, wT_proj, DMODEL, DMODEL);
    transpose_tf32_kernel<<<dim3(INNER / 32,      DMODEL / 32), 256>>>(w_fc,   wT_fc,   DMODEL, INNER);
    transpose_tf32_kernel<<<dim3(DMODEL / 32,     INNER  / 32), 256>>>(w_mlp,  wT_mlp,  INNER,  DMODEL);

    // 1. LN1 (tf32-rounded output)
    ln_kernel<<<ROWS, 256>>>(hidden, g1, be1, x);
    // 2. QKV = x @ w_qkv + b_qkv
    tc_gemm_kernel<EPI_BIAS><<<dim3(3 * DMODEL / 128, ROWS / 128), 256, GSMEM_DYN>>>(
        x, wT_qkv, b_qkv, nullptr, qkv, ROWS, 3 * DMODEL, DMODEL);
    // 3. attention (tf32-rounded output)
    attn_kernel<<<dim3(SEQ / 64, BATCH * NHEADS), 256, attn_smem>>>(qkv, attn);
    // 4. h2 = attn @ w_proj + b_proj + hidden
    tc_gemm_kernel<EPI_RES><<<dim3(DMODEL / 128, ROWS / 128), 256, GSMEM_DYN>>>(
        attn, wT_proj, b_proj, hidden, h2, ROWS, DMODEL, DMODEL);
    // 5. LN2 (tf32-rounded output)
    ln_kernel<<<ROWS, 256>>>(h2, g2, be2, y);
    // 6. fc = gelu(y @ w_fc + b_fc)  (tf32-rounded)
    tc_gemm_kernel<EPI_GELU><<<dim3(INNER / 128, ROWS / 128), 256, GSMEM_DYN>>>(
        y, wT_fc, b_fc, nullptr, fc, ROWS, INNER, DMODEL);
    // 7. out = fc @ w_mlp + b_mlp + h2
    tc_gemm_kernel<EPI_RES><<<dim3(DMODEL / 128, ROWS / 128), 256, GSMEM_DYN>>>(
        fc, wT_mlp, b_mlp, h2, out, ROWS, DMODEL, INNER);
}

// round 7
// speedup vs baseline: 3.1232x; 1.4837x over previous
#include <cuda_runtime.h>
#include <cuda_bf16.h>
#include <math.h>
#include <stdint.h>

// ---------------------------------------------------------------------------
// GPT-2 block. GEMMs + attention via warp-level mma.sync tf32 (sm_100 target:
// no tcgen05). B=2, S=2048, D=1024, H=16, dh=64, INNER=4096
// ---------------------------------------------------------------------------

#define BATCH   2
#define SEQ     2048
#define DMODEL  1024
#define NHEADS  16
#define HDIM    64
#define INNER   4096
#define ROWS    (BATCH * SEQ)          // 4096
#define EPS     1e-5f

// ------------------------- scratch (static device mem) ---------------------
__device__ float g_x   [ROWS * DMODEL];
__device__ float g_qkv [ROWS * 3 * DMODEL];
__device__ float g_attn[ROWS * DMODEL];
__device__ float g_h2  [ROWS * DMODEL];
__device__ float g_y   [ROWS * DMODEL];
__device__ float g_fc  [ROWS * INNER];
__device__ float g_wT  [12 * 1024 * 1024];
#define WT_QKV_OFF  0
#define WT_PROJ_OFF (3072 * 1024)
#define WT_FC_OFF   (WT_PROJ_OFF + 1024 * 1024)
#define WT_MLP_OFF  (WT_FC_OFF + 4096 * 1024)

// ------------------------------ small helpers -------------------------------
__device__ __forceinline__ float tf32r(float x) {
    unsigned r;
    asm("cvt.rna.tf32.f32 %0, %1;" : "=r"(r) : "f"(x));
    return __uint_as_float(r);
}

__device__ __forceinline__ float gelu_exact(float x) {
    return 0.5f * x * (1.0f + erff(x * 0.70710678118654752f));
}

__device__ __forceinline__ uint32_t smem_u32(const void* p) {
    uint32_t a;
    asm("{ .reg .u64 t; cvta.to.shared.u64 t, %1; cvt.u32.u64 %0, t; }"
        : "=r"(a) : "l"(p));
    return a;
}

__device__ __forceinline__ void cpa16(uint32_t dst, const float* src) {
    asm volatile("cp.async.cg.shared.global [%0], [%1], 16;" :: "r"(dst), "l"(src));
}

__device__ __forceinline__ void mma_tf32(
    float& c0, float& c1, float& c2, float& c3,
    uint32_t a0, uint32_t a1, uint32_t a2, uint32_t a3,
    uint32_t b0, uint32_t b1)
{
    asm volatile(
        "mma.sync.aligned.m16n8k8.row.col.f32.tf32.tf32.f32 "
        "{%0,%1,%2,%3}, {%4,%5,%6,%7}, {%8,%9}, {%0,%1,%2,%3};"
        : "+f"(c0), "+f"(c1), "+f"(c2), "+f"(c3)
        : "r"(a0), "r"(a1), "r"(a2), "r"(a3), "r"(b0), "r"(b1));
}

// ------------------------------- LayerNorm ---------------------------------
__global__ void __launch_bounds__(256) ln_kernel(
    const float* __restrict__ in, const float* __restrict__ gamma,
    const float* __restrict__ beta, float* __restrict__ out)
{
    __shared__ float red[16];
    const int row = blockIdx.x;
    const int tid = threadIdx.x;
    const float* x = in + (size_t)row * DMODEL;

    float4 v = *(const float4*)(x + tid * 4);
    float s = v.x + v.y + v.z + v.w;
    float q = v.x * v.x + v.y * v.y + v.z * v.z + v.w * v.w;
    #pragma unroll
    for (int off = 16; off; off >>= 1) {
        s += __shfl_xor_sync(0xffffffffu, s, off);
        q += __shfl_xor_sync(0xffffffffu, q, off);
    }
    const int w = tid >> 5;
    if ((tid & 31) == 0) { red[w] = s; red[8 + w] = q; }
    __syncthreads();
    float st = 0.f, qt = 0.f;
    #pragma unroll
    for (int i = 0; i < 8; i++) { st += red[i]; qt += red[8 + i]; }

    const float mu  = st * (1.0f / DMODEL);
    const float var = qt * (1.0f / DMODEL) - mu * mu;
    const float inv = rsqrtf(var + EPS);

    float4 g = *(const float4*)(gamma + tid * 4);
    float4 b = *(const float4*)(beta  + tid * 4);
    float4 o;
    o.x = tf32r((v.x - mu) * inv * g.x + b.x);
    o.y = tf32r((v.y - mu) * inv * g.y + b.y);
    o.z = tf32r((v.z - mu) * inv * g.z + b.z);
    o.w = tf32r((v.w - mu) * inv * g.w + b.w);
    *(float4*)(out + (size_t)row * DMODEL + tid * 4) = o;
}

// ----------------------- weight transpose (+tf32 round) --------------------
__global__ void __launch_bounds__(256) transpose_tf32_kernel(
    const float* __restrict__ in, float* __restrict__ out, int K, int N)
{
    __shared__ float t[32][33];
    const int n0 = blockIdx.x * 32;
    const int k0 = blockIdx.y * 32;
    const int tx = threadIdx.x & 31;
    const int ty = threadIdx.x >> 5;
    #pragma unroll
    for (int i = 0; i < 32; i += 8)
        t[ty + i][tx] = in[(size_t)(k0 + ty + i) * N + n0 + tx];
    __syncthreads();
    #pragma unroll
    for (int i = 0; i < 32; i += 8)
        out[(size_t)(n0 + ty + i) * K + k0 + tx] = tf32r(t[tx][ty + i]);
}

// ------------------------------ tf32 MMA GEMM -------------------------------
// C[M,N] = A[M,K] @ Bt[N,K]^T (+bias, +res | gelu). 128x128 CTA tile, BK=32,
// 8 warps (2Mx4N), warp tile 64x32. 4-stage cp.async ring, depth-3 prefetch.
#define EPI_BIAS  0    // bias, tf32-rounded output (qkv)
#define EPI_RES   1
#define EPI_GELU  2

#define BK       32
#define SPITCH   36
#define STAGE_FLOATS (2 * 128 * SPITCH)
#define GSTAGES  4
#define GSMEM_DYN (GSTAGES * STAGE_FLOATS * 4)   // 147456 B

template <int EPI>
__global__ void __launch_bounds__(256) tc_gemm_kernel(
    const float* __restrict__ A, const float* __restrict__ Bt,
    const float* __restrict__ bias, const float* __restrict__ res,
    float* __restrict__ C, int M, int N, int K)
{
    extern __shared__ float smf[];

    const int tid   = threadIdx.x;
    const int wid   = tid >> 5;
    const int lane  = tid & 31;
    const int gi    = lane >> 2;
    const int tig   = lane & 3;
    const int warpM = wid >> 2;
    const int warpN = wid & 3;

    const int mrow0 = blockIdx.y * 128;
    const int ncol0 = blockIdx.x * 128;

    const float* Abase = A  + (size_t)mrow0 * K;
    const float* Bbase = Bt + (size_t)ncol0 * K;

    const uint32_t smem_base = smem_u32(smf);

    float acc[4][4][4];
    #pragma unroll
    for (int i = 0; i < 4; i++)
        #pragma unroll
        for (int j = 0; j < 4; j++)
            #pragma unroll
            for (int q = 0; q < 4; q++) acc[i][j][q] = 0.f;

    const int NC = K / BK;

    auto load_stage = [&](int c) {
        const int s = c & (GSTAGES - 1);
        const uint32_t a_st = smem_base + s * STAGE_FLOATS * 4;
        const uint32_t b_st = a_st + 128 * SPITCH * 4;
        const int kof = c * BK;
        #pragma unroll
        for (int i = 0; i < 4; i++) {
            const int lin = tid + i * 256;
            const int r   = lin >> 3;
            const int cc  = lin & 7;
            const uint32_t off = (uint32_t)(r * SPITCH + cc * 4) * 4;
            cpa16(a_st + off, Abase + (size_t)r * K + kof + cc * 4);
            cpa16(b_st + off, Bbase + (size_t)r * K + kof + cc * 4);
        }
    };

    #pragma unroll
    for (int p = 0; p < GSTAGES - 1; p++) {
        load_stage(p);
        asm volatile("cp.async.commit_group;" ::: "memory");
    }

    for (int c = 0; c < NC; c++) {
        asm volatile("cp.async.wait_group %0;" :: "n"(GSTAGES - 2) : "memory");
        __syncthreads();

        if (c + GSTAGES - 1 < NC) load_stage(c + GSTAGES - 1);
        asm volatile("cp.async.commit_group;" ::: "memory");

        const float* As = smf + (c & (GSTAGES - 1)) * STAGE_FLOATS;
        const float* Bs = As + 128 * SPITCH;
        const float* Aw = As + (warpM * 64 + gi) * SPITCH + tig;
        const float* Bw = Bs + (warpN * 32 + gi) * SPITCH + tig;

        #pragma unroll
        for (int ks = 0; ks < BK; ks += 8) {
            uint32_t af[4][4], bf[4][2];
            #pragma unroll
            for (int im = 0; im < 4; im++) {
                const float* p = Aw + im * 16 * SPITCH + ks;
                af[im][0] = __float_as_uint(p[0]);
                af[im][1] = __float_as_uint(p[8 * SPITCH]);
                af[im][2] = __float_as_uint(p[4]);
                af[im][3] = __float_as_uint(p[8 * SPITCH + 4]);
            }
            #pragma unroll
            for (int jn = 0; jn < 4; jn++) {
                const float* p = Bw + jn * 8 * SPITCH + ks;
                bf[jn][0] = __float_as_uint(p[0]);
                bf[jn][1] = __float_as_uint(p[4]);
            }
            #pragma unroll
            for (int im = 0; im < 4; im++)
                #pragma unroll
                for (int jn = 0; jn < 4; jn++)
                    mma_tf32(acc[im][jn][0], acc[im][jn][1],
                             acc[im][jn][2], acc[im][jn][3],
                             af[im][0], af[im][1], af[im][2], af[im][3],
                             bf[jn][0], bf[jn][1]);
        }
    }

    // ---- epilogue ----------------------------------------------------------
    #pragma unroll
    for (int im = 0; im < 4; im++) {
        const int r0 = mrow0 + warpM * 64 + im * 16 + gi;
        #pragma unroll
        for (int half = 0; half < 2; half++) {
            const size_t row = (size_t)(r0 + half * 8);
            float* Crow = C + row * N;
            const float* Rrow = (EPI == EPI_RES) ? (res + row * N) : nullptr;
            #pragma unroll
            for (int jn = 0; jn < 4; jn++) {
                const int col = ncol0 + warpN * 32 + jn * 8 + tig * 2;
                float2 o;
                o.x = acc[im][jn][half * 2 + 0];
                o.y = acc[im][jn][half * 2 + 1];
                float2 bv = *(const float2*)(bias + col);
                o.x += bv.x; o.y += bv.y;
                if (EPI == EPI_RES) {
                    float2 rv = *(const float2*)(Rrow + col);
                    o.x += rv.x; o.y += rv.y;
                }
                if (EPI == EPI_GELU) {
                    o.x = tf32r(gelu_exact(o.x));
                    o.y = tf32r(gelu_exact(o.y));
                }
                if (EPI == EPI_BIAS) {      // qkv: round for attention MMAs
                    o.x = tf32r(o.x);
                    o.y = tf32r(o.y);
                }
                *(float2*)(Crow + col) = o;
            }
        }
    }
}

// ------------------------- Flash attention (tf32 MMA) -----------------------
// CTA: 128 q-rows (8 warps x 16 rows), 64-key tiles. Q frags in registers
// (pre-scaled by 1/8). S and P@V via m16n8k8. P is warp-private smem.
#define KP 68          // K tile pitch (words)
#define VP 72          // V tile pitch
#define PP 68          // P tile pitch (also Q staging)
#define ATTN_SMEM_B ((64 * KP + 64 * VP + 128 * PP) * 4)   // 70656

__global__ void __launch_bounds__(256, 2) attn_kernel(
    const float* __restrict__ qkv, float* __restrict__ out)
{
    extern __shared__ float sm[];
    float* Ks = sm;                   // [64][KP]
    float* Vs = Ks + 64 * KP;         // [64][VP]
    float* Ps = Vs + 64 * VP;         // [128][PP]  (Q staging, then P)

    const int qt  = blockIdx.x;               // 0..15
    const int b   = blockIdx.y >> 4;
    const int h   = blockIdx.y & 15;
    const int tid = threadIdx.x;
    const int wid = tid >> 5;                 // 0..7
    const int lane = tid & 31;
    const int gi  = lane >> 2;                // 0..7
    const int tig = lane & 3;                 // 0..3

    const int q0 = qt * 128;
    const size_t base = (size_t)b * SEQ * (3 * DMODEL);

    // ---- stage Q tile [128][64] into Ps, then build register fragments ----
    const float* Qg = qkv + base + (size_t)q0 * (3 * DMODEL) + h * HDIM;
    for (int idx = tid; idx < 128 * 16; idx += 256) {
        const int r = idx >> 4, c = (idx & 15) << 2;
        float4 v = *(const float4*)(Qg + (size_t)r * (3 * DMODEL) + c);
        float* p = Ps + r * PP + c;
        p[0] = v.x; p[1] = v.y; p[2] = v.z; p[3] = v.w;
    }
    __syncthreads();

    uint32_t qf[8][4];
    {
        const float* Qw  = Ps + (wid * 16 + gi) * PP;
        const float* Qw8 = Qw + 8 * PP;
        #pragma unroll
        for (int ks = 0; ks < 8; ks++) {
            qf[ks][0] = __float_as_uint(Qw [ks * 8 + tig]     * 0.125f);
            qf[ks][1] = __float_as_uint(Qw8[ks * 8 + tig]     * 0.125f);
            qf[ks][2] = __float_as_uint(Qw [ks * 8 + tig + 4] * 0.125f);
            qf[ks][3] = __float_as_uint(Qw8[ks * 8 + tig + 4] * 0.125f);
        }
    }

    float m[2] = {-1e30f, -1e30f};
    float l[2] = {0.f, 0.f};
    float o[8][4];
    #pragma unroll
    for (int jn = 0; jn < 8; jn++)
        #pragma unroll
        for (int q = 0; q < 4; q++) o[jn][q] = 0.f;

    const int qrow_w = q0 + wid * 16;
    const int nkt = qt * 2 + 2;

    for (int kt = 0; kt < nkt; kt++) {
        __syncthreads();   // all warps done with prior K/V (and Q frags @kt=0)

        const float* Kg = qkv + base + (size_t)(kt * 64) * (3 * DMODEL)
                          + DMODEL + h * HDIM;
        const float* Vg = Kg + DMODEL;
        #pragma unroll
        for (int i = 0; i < 4; i++) {
            const int idx = tid + i * 256;          // 0..1023
            const int r = idx >> 4, c = (idx & 15) << 2;
            cpa16(smem_u32(Ks + r * KP + c), Kg + (size_t)r * (3 * DMODEL) + c);
            cpa16(smem_u32(Vs + r * VP + c), Vg + (size_t)r * (3 * DMODEL) + c);
        }
        asm volatile("cp.async.commit_group;" ::: "memory");
        asm volatile("cp.async.wait_group 0;" ::: "memory");
        __syncthreads();

        // ---- S = (Q/8) @ K^T : 16x64 per warp -----------------------------
        float s[8][4];
        #pragma unroll
        for (int jn = 0; jn < 8; jn++)
            #pragma unroll
            for (int q = 0; q < 4; q++) s[jn][q] = 0.f;

        #pragma unroll
        for (int ks = 0; ks < 8; ks++) {
            #pragma unroll
            for (int jn = 0; jn < 8; jn++) {
                const float* kp = Ks + (jn * 8 + gi) * KP + ks * 8 + tig;
                const uint32_t b0 = __float_as_uint(kp[0]);
                const uint32_t b1 = __float_as_uint(kp[4]);
                mma_tf32(s[jn][0], s[jn][1], s[jn][2], s[jn][3],
                         qf[ks][0], qf[ks][1], qf[ks][2], qf[ks][3], b0, b1);
            }
        }

        // ---- causal mask --------------------------------------------------
        if (kt * 64 + 63 > qrow_w) {
            #pragma unroll
            for (int jn = 0; jn < 8; jn++) {
                const int kc = kt * 64 + jn * 8 + tig * 2;
                const int r0 = qrow_w + gi;
                const int r1 = r0 + 8;
                if (kc     > r0) s[jn][0] = -1e30f;
                if (kc + 1 > r0) s[jn][1] = -1e30f;
                if (kc     > r1) s[jn][2] = -1e30f;
                if (kc + 1 > r1) s[jn][3] = -1e30f;
            }
        }

        // ---- online softmax (2 row-slots per thread, quad reductions) -----
        #pragma unroll
        for (int rr = 0; rr < 2; rr++) {
            const int i0 = rr * 2, i1 = rr * 2 + 1;
            float mx = -1e30f;
            #pragma unroll
            for (int jn = 0; jn < 8; jn++)
                mx = fmaxf(mx, fmaxf(s[jn][i0], s[jn][i1]));
            mx = fmaxf(mx, __shfl_xor_sync(0xffffffffu, mx, 1));
            mx = fmaxf(mx, __shfl_xor_sync(0xffffffffu, mx, 2));
            const float mn = fmaxf(m[rr], mx);
            const float al = __expf(m[rr] - mn);
            float rs = 0.f;
            #pragma unroll
            for (int jn = 0; jn < 8; jn++) {
                const float e0 = __expf(s[jn][i0] - mn);
                const float e1 = __expf(s[jn][i1] - mn);
                s[jn][i0] = e0; s[jn][i1] = e1;
                rs += e0 + e1;
            }
            rs += __shfl_xor_sync(0xffffffffu, rs, 1);
            rs += __shfl_xor_sync(0xffffffffu, rs, 2);
            l[rr] = l[rr] * al + rs;
            m[rr] = mn;
            #pragma unroll
            for (int jn = 0; jn < 8; jn++) { o[jn][i0] *= al; o[jn][i1] *= al; }
        }

        // ---- P -> warp-private smem (tf32-rounded) ------------------------
        {
            float* Pw = Ps + (wid * 16 + gi) * PP;
            #pragma unroll
            for (int jn = 0; jn < 8; jn++) {
                float2 p0 = {tf32r(s[jn][0]), tf32r(s[jn][1])};
                float2 p1 = {tf32r(s[jn][2]), tf32r(s[jn][3])};
                *(float2*)(Pw + jn * 8 + tig * 2)          = p0;
                *(float2*)(Pw + 8 * PP + jn * 8 + tig * 2) = p1;
            }
        }
        __syncwarp();

        // ---- O += P @ V ---------------------------------------------------
        {
            const float* Pr = Ps + (wid * 16 + gi) * PP;
            #pragma unroll
            for (int ks = 0; ks < 8; ks++) {
                const uint32_t a0 = __float_as_uint(Pr[ks * 8 + tig]);
                const uint32_t a1 = __float_as_uint(Pr[8 * PP + ks * 8 + tig]);
                const uint32_t a2 = __float_as_uint(Pr[ks * 8 + tig + 4]);
                const uint32_t a3 = __float_as_uint(Pr[8 * PP + ks * 8 + tig + 4]);
                #pragma unroll
                for (int jn = 0; jn < 8; jn++) {
                    const uint32_t b0 =
                        __float_as_uint(Vs[(ks * 8 + tig) * VP + jn * 8 + gi]);
                    const uint32_t b1 =
                        __float_as_uint(Vs[(ks * 8 + tig + 4) * VP + jn * 8 + gi]);
                    mma_tf32(o[jn][0], o[jn][1], o[jn][2], o[jn][3],
                             a0, a1, a2, a3, b0, b1);
                }
            }
        }
        __syncwarp();
    }

    // ---- normalize + store (tf32-rounded: feeds proj GEMM) -----------------
    const float inv0 = 1.0f / l[0];
    const float inv1 = 1.0f / l[1];
    float* O0 = out + ((size_t)b * SEQ + qrow_w + gi)     * DMODEL + h * HDIM;
    float* O1 = out + ((size_t)b * SEQ + qrow_w + gi + 8) * DMODEL + h * HDIM;
    #pragma unroll
    for (int jn = 0; jn < 8; jn++) {
        float2 v0 = {tf32r(o[jn][0] * inv0), tf32r(o[jn][1] * inv0)};
        float2 v1 = {tf32r(o[jn][2] * inv1), tf32r(o[jn][3] * inv1)};
        *(float2*)(O0 + jn * 8 + tig * 2) = v0;
        *(float2*)(O1 + jn * 8 + tig * 2) = v1;
    }
}

// ------------------------------- launcher -----------------------------------
extern "C" void kernel_launch(void* const* d_in, const int* in_sizes, int n_in,
                              void* d_out, int out_size)
{
    const float* hidden = (const float*)d_in[0];
    const float* w_qkv  = (const float*)d_in[1];
    const float* b_qkv  = (const float*)d_in[2];
    const float* g1     = (const float*)d_in[3];
    const float* be1    = (const float*)d_in[4];
    const float* w_proj = (const float*)d_in[5];
    const float* b_proj = (const float*)d_in[6];
    const float* g2     = (const float*)d_in[7];
    const float* be2    = (const float*)d_in[8];
    const float* w_fc   = (const float*)d_in[9];
    const float* b_fc   = (const float*)d_in[10];
    const float* w_mlp  = (const float*)d_in[11];
    const float* b_mlp  = (const float*)d_in[12];
    float* out = (float*)d_out;

    float *x, *qkv, *attn, *h2, *y, *fc, *wT;
    cudaGetSymbolAddress((void**)&x,    g_x);
    cudaGetSymbolAddress((void**)&qkv,  g_qkv);
    cudaGetSymbolAddress((void**)&attn, g_attn);
    cudaGetSymbolAddress((void**)&h2,   g_h2);
    cudaGetSymbolAddress((void**)&y,    g_y);
    cudaGetSymbolAddress((void**)&fc,   g_fc);
    cudaGetSymbolAddress((void**)&wT,   g_wT);

    float* wT_qkv  = wT + WT_QKV_OFF;
    float* wT_proj = wT + WT_PROJ_OFF;
    float* wT_fc   = wT + WT_FC_OFF;
    float* wT_mlp  = wT + WT_MLP_OFF;

    cudaFuncSetAttribute(attn_kernel,
                         cudaFuncAttributeMaxDynamicSharedMemorySize, ATTN_SMEM_B);
    cudaFuncSetAttribute(tc_gemm_kernel<EPI_BIAS>,
                         cudaFuncAttributeMaxDynamicSharedMemorySize, GSMEM_DYN);
    cudaFuncSetAttribute(tc_gemm_kernel<EPI_RES>,
                         cudaFuncAttributeMaxDynamicSharedMemorySize, GSMEM_DYN);
    cudaFuncSetAttribute(tc_gemm_kernel<EPI_GELU>,
                         cudaFuncAttributeMaxDynamicSharedMemorySize, GSMEM_DYN);

    // 0. transpose + tf32-round weights
    transpose_tf32_kernel<<<dim3(3 * DMODEL / 32, DMODEL / 32), 256>>>(w_qkv,  wT_qkv,  DMODEL, 3 * DMODEL);
    transpose_tf32_kernel<<<dim3(DMODEL / 32,     DMODEL / 32), 256>>>(w_proj, wT_proj, DMODEL, DMODEL);
    transpose_tf32_kernel<<<dim3(INNER / 32,      DMODEL / 32), 256>>>(w_fc,   wT_fc,   DMODEL, INNER);
    transpose_tf32_kernel<<<dim3(DMODEL / 32,     INNER  / 32), 256>>>(w_mlp,  wT_mlp,  INNER,  DMODEL);

    // 1. LN1
    ln_kernel<<<ROWS, 256>>>(hidden, g1, be1, x);
    // 2. QKV = x @ w_qkv + b_qkv  (tf32-rounded output)
    tc_gemm_kernel<EPI_BIAS><<<dim3(3 * DMODEL / 128, ROWS / 128), 256, GSMEM_DYN>>>(
        x, wT_qkv, b_qkv, nullptr, qkv, ROWS, 3 * DMODEL, DMODEL);
    // 3. attention (tf32-rounded output)
    attn_kernel<<<dim3(SEQ / 128, BATCH * NHEADS), 256, ATTN_SMEM_B>>>(qkv, attn);
    // 4. h2 = attn @ w_proj + b_proj + hidden
    tc_gemm_kernel<EPI_RES><<<dim3(DMODEL / 128, ROWS / 128), 256, GSMEM_DYN>>>(
        attn, wT_proj, b_proj, hidden, h2, ROWS, DMODEL, DMODEL);
    // 5. LN2
    ln_kernel<<<ROWS, 256>>>(h2, g2, be2, y);
    // 6. fc = gelu(y @ w_fc + b_fc)
    tc_gemm_kernel<EPI_GELU><<<dim3(INNER / 128, ROWS / 128), 256, GSMEM_DYN>>>(
        y, wT_fc, b_fc, nullptr, fc, ROWS, INNER, DMODEL);
    // 7. out = fc @ w_mlp + b_mlp + h2
    tc_gemm_kernel<EPI_RES><<<dim3(DMODEL / 128, ROWS / 128), 256, GSMEM_DYN>>>(
        fc, wT_mlp, b_mlp, h2, out, ROWS, DMODEL, INNER);
}

// round 8
// speedup vs baseline: 5.7086x; 1.8278x over previous
#include <cuda_runtime.h>
#include <cuda_fp16.h>
#include <math.h>
#include <stdint.h>

// ---------------------------------------------------------------------------
// GPT-2 block, fp16 mma.sync (m16n8k16) everywhere. fp16 mantissa == tf32
// mantissa (10 bits) -> accuracy matches tf32 (~1.9e-4) at 2x MMA K-depth
// and half the SMEM/global traffic.
// B=2, S=2048, D=1024, H=16, dh=64, INNER=4096
// ---------------------------------------------------------------------------

#define BATCH   2
#define SEQ     2048
#define DMODEL  1024
#define NHEADS  16
#define HDIM    64
#define INNER   4096
#define ROWS    (BATCH * SEQ)
#define EPS     1e-5f

// ------------------------- scratch (static device mem) ---------------------
__device__ __half g_x   [ROWS * DMODEL];
__device__ __half g_qkv [ROWS * 3 * DMODEL];
__device__ __half g_vT  [BATCH * NHEADS * HDIM * SEQ];
__device__ __half g_attn[ROWS * DMODEL];
__device__ float  g_h2  [ROWS * DMODEL];
__device__ __half g_y   [ROWS * DMODEL];
__device__ __half g_fc  [ROWS * INNER];
__device__ __half g_wT  [12 * 1024 * 1024];
#define WT_QKV_OFF  0
#define WT_PROJ_OFF (3072 * 1024)
#define WT_FC_OFF   (WT_PROJ_OFF + 1024 * 1024)
#define WT_MLP_OFF  (WT_FC_OFF + 4096 * 1024)

// ------------------------------ small helpers -------------------------------
__device__ __forceinline__ float gelu_exact(float x) {
    return 0.5f * x * (1.0f + erff(x * 0.70710678118654752f));
}

__device__ __forceinline__ uint32_t smem_u32(const void* p) {
    uint32_t a;
    asm("{ .reg .u64 t; cvta.to.shared.u64 t, %1; cvt.u32.u64 %0, t; }"
        : "=r"(a) : "l"(p));
    return a;
}

__device__ __forceinline__ void cpa16(uint32_t dst, const void* src) {
    asm volatile("cp.async.cg.shared.global [%0], [%1], 16;" :: "r"(dst), "l"(src));
}

__device__ __forceinline__ void mma_f16(
    float& c0, float& c1, float& c2, float& c3,
    uint32_t a0, uint32_t a1, uint32_t a2, uint32_t a3,
    uint32_t b0, uint32_t b1)
{
    asm volatile(
        "mma.sync.aligned.m16n8k16.row.col.f32.f16.f16.f32 "
        "{%0,%1,%2,%3}, {%4,%5,%6,%7}, {%8,%9}, {%0,%1,%2,%3};"
        : "+f"(c0), "+f"(c1), "+f"(c2), "+f"(c3)
        : "r"(a0), "r"(a1), "r"(a2), "r"(a3), "r"(b0), "r"(b1));
}

// ------------------------------- LayerNorm ---------------------------------
__global__ void __launch_bounds__(256) ln_kernel(
    const float* __restrict__ in, const float* __restrict__ gamma,
    const float* __restrict__ beta, __half* __restrict__ out)
{
    __shared__ float red[16];
    const int row = blockIdx.x;
    const int tid = threadIdx.x;
    const float* x = in + (size_t)row * DMODEL;

    float4 v = *(const float4*)(x + tid * 4);
    float s = v.x + v.y + v.z + v.w;
    float q = v.x * v.x + v.y * v.y + v.z * v.z + v.w * v.w;
    #pragma unroll
    for (int off = 16; off; off >>= 1) {
        s += __shfl_xor_sync(0xffffffffu, s, off);
        q += __shfl_xor_sync(0xffffffffu, q, off);
    }
    const int w = tid >> 5;
    if ((tid & 31) == 0) { red[w] = s; red[8 + w] = q; }
    __syncthreads();
    float st = 0.f, qt = 0.f;
    #pragma unroll
    for (int i = 0; i < 8; i++) { st += red[i]; qt += red[8 + i]; }

    const float mu  = st * (1.0f / DMODEL);
    const float var = qt * (1.0f / DMODEL) - mu * mu;
    const float inv = rsqrtf(var + EPS);

    float4 g = *(const float4*)(gamma + tid * 4);
    float4 b = *(const float4*)(beta  + tid * 4);
    __half2 p0 = __floats2half2_rn((v.x - mu) * inv * g.x + b.x,
                                   (v.y - mu) * inv * g.y + b.y);
    __half2 p1 = __floats2half2_rn((v.z - mu) * inv * g.z + b.z,
                                   (v.w - mu) * inv * g.w + b.w);
    uint2 pk;
    pk.x = *(uint32_t*)&p0;
    pk.y = *(uint32_t*)&p1;
    *(uint2*)(out + (size_t)row * DMODEL + tid * 4) = pk;
}

// ----------------------- weight transpose (+fp16 round) --------------------
// in: [K,N] f32 row-major -> out: [N,K] half row-major
__global__ void __launch_bounds__(256) transpose_h_kernel(
    const float* __restrict__ in, __half* __restrict__ out, int K, int N)
{
    __shared__ float t[32][33];
    const int n0 = blockIdx.x * 32;
    const int k0 = blockIdx.y * 32;
    const int tx = threadIdx.x & 31;
    const int ty = threadIdx.x >> 5;
    #pragma unroll
    for (int i = 0; i < 32; i += 8)
        t[ty + i][tx] = in[(size_t)(k0 + ty + i) * N + n0 + tx];
    __syncthreads();
    #pragma unroll
    for (int i = 0; i < 32; i += 8)
        out[(size_t)(n0 + ty + i) * K + k0 + tx] = __float2half(t[tx][ty + i]);
}

// ------------------------------ fp16 MMA GEMM -------------------------------
// C[M,N] = A[M,K] @ Bt[N,K]^T (+bias, +res | gelu). 128x128 CTA tile, BK=64,
// 8 warps (2Mx4N), warp tile 64x32, m16n8k16. 4-stage cp.async ring.
#define EPI_QKV   0    // half out; V third written transposed to vT
#define EPI_RES   1    // float out, +f32 residual
#define EPI_GELU  2    // half out, gelu

#define BKH      64
#define SPH      72                       // halves per smem row (conflict-free)
#define SPW      (SPH / 2)                // 36 words
#define TILE_H   (128 * SPH)              // 9216 halves
#define STAGE_H  (2 * TILE_H)
#define GSTAGES  4
#define GSMEM_DYN (GSTAGES * STAGE_H * 2) // 147456 B

template <int EPI>
__global__ void __launch_bounds__(256) hgemm_kernel(
    const __half* __restrict__ A, const __half* __restrict__ Bt,
    const float* __restrict__ bias, const float* __restrict__ res,
    void* __restrict__ Cv, __half* __restrict__ vT, int M, int N, int K)
{
    extern __shared__ __half smh[];

    const int tid   = threadIdx.x;
    const int wid   = tid >> 5;
    const int lane  = tid & 31;
    const int gi    = lane >> 2;
    const int tig   = lane & 3;
    const int warpM = wid >> 2;
    const int warpN = wid & 3;

    const int mrow0 = blockIdx.y * 128;
    const int ncol0 = blockIdx.x * 128;

    const __half* Abase = A  + (size_t)mrow0 * K;
    const __half* Bbase = Bt + (size_t)ncol0 * K;

    const uint32_t smem_base = smem_u32(smh);

    float acc[4][4][4];
    #pragma unroll
    for (int i = 0; i < 4; i++)
        #pragma unroll
        for (int j = 0; j < 4; j++)
            #pragma unroll
            for (int q = 0; q < 4; q++) acc[i][j][q] = 0.f;

    const int NC = K / BKH;

    auto load_stage = [&](int c) {
        const int s = c & (GSTAGES - 1);
        const uint32_t a_st = smem_base + s * STAGE_H * 2;
        const uint32_t b_st = a_st + TILE_H * 2;
        const int kof = c * BKH;
        #pragma unroll
        for (int i = 0; i < 4; i++) {
            const int lin = tid + i * 256;     // 0..1023
            const int r   = lin >> 3;
            const int cc  = lin & 7;
            const uint32_t off = (uint32_t)(r * (SPH * 2) + cc * 16);
            cpa16(a_st + off, Abase + (size_t)r * K + kof + cc * 8);
            cpa16(b_st + off, Bbase + (size_t)r * K + kof + cc * 8);
        }
    };

    #pragma unroll
    for (int p = 0; p < GSTAGES - 1; p++) {
        load_stage(p);
        asm volatile("cp.async.commit_group;" ::: "memory");
    }

    for (int c = 0; c < NC; c++) {
        asm volatile("cp.async.wait_group %0;" :: "n"(GSTAGES - 2) : "memory");
        __syncthreads();

        if (c + GSTAGES - 1 < NC) load_stage(c + GSTAGES - 1);
        asm volatile("cp.async.commit_group;" ::: "memory");

        const uint32_t* As32 = (const uint32_t*)(smh + (c & (GSTAGES - 1)) * STAGE_H);
        const uint32_t* Bs32 = As32 + TILE_H / 2;
        const uint32_t* Aw = As32 + (warpM * 64 + gi) * SPW + tig;
        const uint32_t* Bw = Bs32 + (warpN * 32 + gi) * SPW + tig;

        #pragma unroll
        for (int ks = 0; ks < 4; ks++) {
            uint32_t af[4][4], bf[4][2];
            #pragma unroll
            for (int im = 0; im < 4; im++) {
                const uint32_t* p = Aw + im * 16 * SPW + ks * 8;
                af[im][0] = p[0];
                af[im][1] = p[8 * SPW];
                af[im][2] = p[4];
                af[im][3] = p[8 * SPW + 4];
            }
            #pragma unroll
            for (int jn = 0; jn < 4; jn++) {
                const uint32_t* p = Bw + jn * 8 * SPW + ks * 8;
                bf[jn][0] = p[0];
                bf[jn][1] = p[4];
            }
            #pragma unroll
            for (int im = 0; im < 4; im++)
                #pragma unroll
                for (int jn = 0; jn < 4; jn++)
                    mma_f16(acc[im][jn][0], acc[im][jn][1],
                            acc[im][jn][2], acc[im][jn][3],
                            af[im][0], af[im][1], af[im][2], af[im][3],
                            bf[jn][0], bf[jn][1]);
        }
    }

    // ---- epilogue ----------------------------------------------------------
    const bool vpart = (EPI == EPI_QKV) && (ncol0 >= 2 * DMODEL);
    #pragma unroll
    for (int im = 0; im < 4; im++) {
        const int r0 = mrow0 + warpM * 64 + im * 16 + gi;
        #pragma unroll
        for (int hf = 0; hf < 2; hf++) {
            const size_t row = (size_t)(r0 + hf * 8);
            #pragma unroll
            for (int jn = 0; jn < 4; jn++) {
                const int col = ncol0 + warpN * 32 + jn * 8 + tig * 2;
                float ox = acc[im][jn][hf * 2 + 0];
                float oy = acc[im][jn][hf * 2 + 1];
                float2 bv = *(const float2*)(bias + col);
                ox += bv.x; oy += bv.y;
                if (EPI == EPI_RES) {
                    float2 rv = *(const float2*)(res + row * N + col);
                    float2 o2 = {ox + rv.x, oy + rv.y};
                    *(float2*)((float*)Cv + row * N + col) = o2;
                } else if (EPI == EPI_GELU) {
                    __half2 hv = __floats2half2_rn(gelu_exact(ox), gelu_exact(oy));
                    *(__half2*)((__half*)Cv + row * N + col) = hv;
                } else {  // EPI_QKV
                    if (vpart) {
                        const int vcol = col - 2 * DMODEL;
                        const int hh = vcol >> 6, d = vcol & 63;
                        const int bb = (int)(row >> 11), tok = (int)(row & 2047);
                        __half* vp = vT +
                            ((size_t)((bb * NHEADS + hh) * HDIM + d)) * SEQ + tok;
                        vp[0]   = __float2half(ox);
                        vp[SEQ] = __float2half(oy);
                    } else {
                        __half2 hv = __floats2half2_rn(ox, oy);
                        *(__half2*)((__half*)Cv + row * N + col) = hv;
                    }
                }
            }
        }
    }
}

// ------------------------- Flash attention (fp16 MMA) -----------------------
// CTA: 128 q-rows (8 warps x 16 rows), 64-key tiles, double-buffered K/V.
// K from qkv [tok][d]; V from vT [d][tok] (token pairs contiguous for B-frags).
#define KVH    (64 * SPH)                       // 4608 halves per tile
#define P_OFF  (4 * KVH)
#define ATTN_SMEM_B ((4 * KVH + 128 * SPH) * 2) // 55296 B

__global__ void __launch_bounds__(256, 2) attn_kernel(
    const __half* __restrict__ qkv, const __half* __restrict__ vT,
    __half* __restrict__ out)
{
    extern __shared__ __half smh[];
    const uint32_t smem_base = smem_u32(smh);

    const int qt  = blockIdx.x;
    const int b   = blockIdx.y >> 4;
    const int h   = blockIdx.y & 15;
    const int tid = threadIdx.x;
    const int wid = tid >> 5;
    const int lane = tid & 31;
    const int gi  = lane >> 2;
    const int tig = lane & 3;

    const int q0 = qt * 128;
    const int qrow_w = q0 + wid * 16;
    const int nkt = qt * 2 + 2;

    auto load_tile = [&](int kt) {
        const int st = kt & 1;
        const __half* Kg = qkv + ((size_t)(b * SEQ + kt * 64)) * 3072
                           + DMODEL + h * HDIM;
        const __half* Vg = vT + ((size_t)((b * NHEADS + h) * HDIM)) * SEQ + kt * 64;
        const uint32_t Kd = smem_base + st * (KVH * 2);
        const uint32_t Vd = smem_base + (2 + st) * (KVH * 2);
        #pragma unroll
        for (int i = 0; i < 4; i++) {
            const int idx = tid + i * 256;
            if (idx < 512) {
                const int r = idx >> 3, cc = idx & 7;
                cpa16(Kd + r * (SPH * 2) + cc * 16, Kg + (size_t)r * 3072 + cc * 8);
            } else {
                const int j = idx - 512;
                const int r = j >> 3, cc = j & 7;
                cpa16(Vd + r * (SPH * 2) + cc * 16, Vg + (size_t)r * SEQ + cc * 8);
            }
        }
    };

    // ---- stage Q into P area + prefetch tile 0 ----
    {
        const __half* Qg = qkv + ((size_t)(b * SEQ + q0)) * 3072 + h * HDIM;
        const uint32_t Pd = smem_base + P_OFF * 2;
        #pragma unroll
        for (int i = 0; i < 4; i++) {
            const int idx = tid + i * 256;
            const int r = idx >> 3, cc = idx & 7;
            cpa16(Pd + r * (SPH * 2) + cc * 16, Qg + (size_t)r * 3072 + cc * 8);
        }
        asm volatile("cp.async.commit_group;" ::: "memory");
        load_tile(0);
        asm volatile("cp.async.commit_group;" ::: "memory");
        asm volatile("cp.async.wait_group 0;" ::: "memory");
        __syncthreads();
    }

    // ---- Q fragments (raw; 1/8 applied on f32 scores) ----
    uint32_t qf[4][4];
    const uint32_t* Pw32 = (const uint32_t*)(smh + P_OFF)
                           + (wid * 16 + gi) * SPW + tig;
    #pragma unroll
    for (int ks = 0; ks < 4; ks++) {
        qf[ks][0] = Pw32[ks * 8];
        qf[ks][1] = Pw32[8 * SPW + ks * 8];
        qf[ks][2] = Pw32[ks * 8 + 4];
        qf[ks][3] = Pw32[8 * SPW + ks * 8 + 4];
    }

    float m[2] = {-1e30f, -1e30f};
    float l[2] = {0.f, 0.f};
    float o[8][4];
    #pragma unroll
    for (int jn = 0; jn < 8; jn++)
        #pragma unroll
        for (int q = 0; q < 4; q++) o[jn][q] = 0.f;

    for (int kt = 0; kt < nkt; kt++) {
        if (kt > 0) {
            asm volatile("cp.async.wait_group 0;" ::: "memory");
            __syncthreads();
        }
        if (kt + 1 < nkt) {
            load_tile(kt + 1);
            asm volatile("cp.async.commit_group;" ::: "memory");
        }

        const int st = kt & 1;
        const uint32_t* Ks32 = (const uint32_t*)(smh + st * KVH);
        const uint32_t* Vs32 = (const uint32_t*)(smh + (2 + st) * KVH);

        // ---- S = Q @ K^T ----
        float s[8][4];
        #pragma unroll
        for (int jn = 0; jn < 8; jn++)
            #pragma unroll
            for (int q = 0; q < 4; q++) s[jn][q] = 0.f;

        #pragma unroll
        for (int ks = 0; ks < 4; ks++) {
            #pragma unroll
            for (int jn = 0; jn < 8; jn++) {
                const uint32_t* kp = Ks32 + (jn * 8 + gi) * SPW + ks * 8 + tig;
                mma_f16(s[jn][0], s[jn][1], s[jn][2], s[jn][3],
                        qf[ks][0], qf[ks][1], qf[ks][2], qf[ks][3],
                        kp[0], kp[4]);
            }
        }

        // ---- scale + causal mask ----
        #pragma unroll
        for (int jn = 0; jn < 8; jn++)
            #pragma unroll
            for (int q = 0; q < 4; q++) s[jn][q] *= 0.125f;

        if (kt * 64 + 63 > qrow_w) {
            #pragma unroll
            for (int jn = 0; jn < 8; jn++) {
                const int kc = kt * 64 + jn * 8 + tig * 2;
                const int r0 = qrow_w + gi;
                const int r1 = r0 + 8;
                if (kc     > r0) s[jn][0] = -1e30f;
                if (kc + 1 > r0) s[jn][1] = -1e30f;
                if (kc     > r1) s[jn][2] = -1e30f;
                if (kc + 1 > r1) s[jn][3] = -1e30f;
            }
        }

        // ---- online softmax ----
        #pragma unroll
        for (int rr = 0; rr < 2; rr++) {
            const int i0 = rr * 2, i1 = rr * 2 + 1;
            float mx = -1e30f;
            #pragma unroll
            for (int jn = 0; jn < 8; jn++)
                mx = fmaxf(mx, fmaxf(s[jn][i0], s[jn][i1]));
            mx = fmaxf(mx, __shfl_xor_sync(0xffffffffu, mx, 1));
            mx = fmaxf(mx, __shfl_xor_sync(0xffffffffu, mx, 2));
            const float mn = fmaxf(m[rr], mx);
            const float al = __expf(m[rr] - mn);
            float rs = 0.f;
            #pragma unroll
            for (int jn = 0; jn < 8; jn++) {
                const float e0 = __expf(s[jn][i0] - mn);
                const float e1 = __expf(s[jn][i1] - mn);
                s[jn][i0] = e0; s[jn][i1] = e1;
                rs += e0 + e1;
            }
            rs += __shfl_xor_sync(0xffffffffu, rs, 1);
            rs += __shfl_xor_sync(0xffffffffu, rs, 2);
            l[rr] = l[rr] * al + rs;
            m[rr] = mn;
            #pragma unroll
            for (int jn = 0; jn < 8; jn++) { o[jn][i0] *= al; o[jn][i1] *= al; }
        }

        // ---- P -> warp-private smem (half) ----
        {
            uint32_t* Pst = (uint32_t*)(smh + P_OFF) + (wid * 16 + gi) * SPW;
            #pragma unroll
            for (int jn = 0; jn < 8; jn++) {
                __half2 p0 = __floats2half2_rn(s[jn][0], s[jn][1]);
                __half2 p1 = __floats2half2_rn(s[jn][2], s[jn][3]);
                Pst[jn * 4 + tig]           = *(uint32_t*)&p0;
                Pst[8 * SPW + jn * 4 + tig] = *(uint32_t*)&p1;
            }
        }
        __syncwarp();

        // ---- O += P @ V  (V tile is [d][tok]) ----
        #pragma unroll
        for (int ks = 0; ks < 4; ks++) {
            const uint32_t a0 = Pw32[ks * 8];
            const uint32_t a1 = Pw32[8 * SPW + ks * 8];
            const uint32_t a2 = Pw32[ks * 8 + 4];
            const uint32_t a3 = Pw32[8 * SPW + ks * 8 + 4];
            #pragma unroll
            for (int jn = 0; jn < 8; jn++) {
                const uint32_t* vp = Vs32 + (jn * 8 + gi) * SPW + ks * 8 + tig;
                mma_f16(o[jn][0], o[jn][1], o[jn][2], o[jn][3],
                        a0, a1, a2, a3, vp[0], vp[4]);
            }
        }
        __syncwarp();
    }

    // ---- normalize + store half ----
    const float inv0 = 1.0f / l[0];
    const float inv1 = 1.0f / l[1];
    __half* O0 = out + ((size_t)(b * SEQ) + qrow_w + gi)     * DMODEL + h * HDIM;
    __half* O1 = out + ((size_t)(b * SEQ) + qrow_w + gi + 8) * DMODEL + h * HDIM;
    #pragma unroll
    for (int jn = 0; jn < 8; jn++) {
        __half2 v0 = __floats2half2_rn(o[jn][0] * inv0, o[jn][1] * inv0);
        __half2 v1 = __floats2half2_rn(o[jn][2] * inv1, o[jn][3] * inv1);
        *(__half2*)(O0 + jn * 8 + tig * 2) = v0;
        *(__half2*)(O1 + jn * 8 + tig * 2) = v1;
    }
}

// ------------------------------- launcher -----------------------------------
extern "C" void kernel_launch(void* const* d_in, const int* in_sizes, int n_in,
                              void* d_out, int out_size)
{
    const float* hidden = (const float*)d_in[0];
    const float* w_qkv  = (const float*)d_in[1];
    const float* b_qkv  = (const float*)d_in[2];
    const float* g1     = (const float*)d_in[3];
    const float* be1    = (const float*)d_in[4];
    const float* w_proj = (const float*)d_in[5];
    const float* b_proj = (const float*)d_in[6];
    const float* g2     = (const float*)d_in[7];
    const float* be2    = (const float*)d_in[8];
    const float* w_fc   = (const float*)d_in[9];
    const float* b_fc   = (const float*)d_in[10];
    const float* w_mlp  = (const float*)d_in[11];
    const float* b_mlp  = (const float*)d_in[12];
    float* out = (float*)d_out;

    __half *x, *qkv, *vT, *attn, *y, *fc, *wT;
    float  *h2;
    cudaGetSymbolAddress((void**)&x,    g_x);
    cudaGetSymbolAddress((void**)&qkv,  g_qkv);
    cudaGetSymbolAddress((void**)&vT,   g_vT);
    cudaGetSymbolAddress((void**)&attn, g_attn);
    cudaGetSymbolAddress((void**)&h2,   g_h2);
    cudaGetSymbolAddress((void**)&y,    g_y);
    cudaGetSymbolAddress((void**)&fc,   g_fc);
    cudaGetSymbolAddress((void**)&wT,   g_wT);

    __half* wT_qkv  = wT + WT_QKV_OFF;
    __half* wT_proj = wT + WT_PROJ_OFF;
    __half* wT_fc   = wT + WT_FC_OFF;
    __half* wT_mlp  = wT + WT_MLP_OFF;

    cudaFuncSetAttribute(attn_kernel,
                         cudaFuncAttributeMaxDynamicSharedMemorySize, ATTN_SMEM_B);
    cudaFuncSetAttribute(hgemm_kernel<EPI_QKV>,
                         cudaFuncAttributeMaxDynamicSharedMemorySize, GSMEM_DYN);
    cudaFuncSetAttribute(hgemm_kernel<EPI_RES>,
                         cudaFuncAttributeMaxDynamicSharedMemorySize, GSMEM_DYN);
    cudaFuncSetAttribute(hgemm_kernel<EPI_GELU>,
                         cudaFuncAttributeMaxDynamicSharedMemorySize, GSMEM_DYN);

    // 0. transpose + round weights to half
    transpose_h_kernel<<<dim3(3 * DMODEL / 32, DMODEL / 32), 256>>>(w_qkv,  wT_qkv,  DMODEL, 3 * DMODEL);
    transpose_h_kernel<<<dim3(DMODEL / 32,     DMODEL / 32), 256>>>(w_proj, wT_proj, DMODEL, DMODEL);
    transpose_h_kernel<<<dim3(INNER / 32,      DMODEL / 32), 256>>>(w_fc,   wT_fc,   DMODEL, INNER);
    transpose_h_kernel<<<dim3(DMODEL / 32,     INNER  / 32), 256>>>(w_mlp,  wT_mlp,  INNER,  DMODEL);

    // 1. LN1 -> half
    ln_kernel<<<ROWS, 256>>>(hidden, g1, be1, x);
    // 2. QKV (Q,K -> qkv half; V -> vT transposed)
    hgemm_kernel<EPI_QKV><<<dim3(3 * DMODEL / 128, ROWS / 128), 256, GSMEM_DYN>>>(
        x, wT_qkv, b_qkv, nullptr, qkv, vT, ROWS, 3 * DMODEL, DMODEL);
    // 3. attention -> half
    attn_kernel<<<dim3(SEQ / 128, BATCH * NHEADS), 256, ATTN_SMEM_B>>>(qkv, vT, attn);
    // 4. h2 = attn @ w_proj + b_proj + hidden  (f32)
    hgemm_kernel<EPI_RES><<<dim3(DMODEL / 128, ROWS / 128), 256, GSMEM_DYN>>>(
        attn, wT_proj, b_proj, hidden, h2, nullptr, ROWS, DMODEL, DMODEL);
    // 5. LN2 -> half
    ln_kernel<<<ROWS, 256>>>(h2, g2, be2, y);
    // 6. fc = gelu(y @ w_fc + b_fc) -> half
    hgemm_kernel<EPI_GELU><<<dim3(INNER / 128, ROWS / 128), 256, GSMEM_DYN>>>(
        y, wT_fc, b_fc, nullptr, fc, nullptr, ROWS, INNER, DMODEL);
    // 7. out = fc @ w_mlp + b_mlp + h2  (f32)
    hgemm_kernel<EPI_RES><<<dim3(DMODEL / 128, ROWS / 128), 256, GSMEM_DYN>>>(
        fc, wT_mlp, b_mlp, h2, out, nullptr, ROWS, DMODEL, INNER);
}

// round 9
// speedup vs baseline: 6.2302x; 1.0914x over previous
#include <cuda_runtime.h>
#include <cuda_fp16.h>
#include <math.h>
#include <stdint.h>

// ---------------------------------------------------------------------------
// GPT-2 block, fp16 mma.sync (m16n8k16). R9: fused prep kernel (4 transposes
// + LN1 in one launch), 3-stage GEMM ring at 2 CTAs/SM.
// B=2, S=2048, D=1024, H=16, dh=64, INNER=4096
// ---------------------------------------------------------------------------

#define BATCH   2
#define SEQ     2048
#define DMODEL  1024
#define NHEADS  16
#define HDIM    64
#define INNER   4096
#define ROWS    (BATCH * SEQ)
#define EPS     1e-5f

// ------------------------- scratch (static device mem) ---------------------
__device__ __half g_x   [ROWS * DMODEL];
__device__ __half g_qkv [ROWS * 3 * DMODEL];
__device__ __half g_vT  [BATCH * NHEADS * HDIM * SEQ];
__device__ __half g_attn[ROWS * DMODEL];
__device__ float  g_h2  [ROWS * DMODEL];
__device__ __half g_y   [ROWS * DMODEL];
__device__ __half g_fc  [ROWS * INNER];
__device__ __half g_wT  [12 * 1024 * 1024];
#define WT_QKV_OFF  0
#define WT_PROJ_OFF (3072 * 1024)
#define WT_FC_OFF   (WT_PROJ_OFF + 1024 * 1024)
#define WT_MLP_OFF  (WT_FC_OFF + 4096 * 1024)

// ------------------------------ small helpers -------------------------------
__device__ __forceinline__ float gelu_exact(float x) {
    return 0.5f * x * (1.0f + erff(x * 0.70710678118654752f));
}

__device__ __forceinline__ uint32_t smem_u32(const void* p) {
    uint32_t a;
    asm("{ .reg .u64 t; cvta.to.shared.u64 t, %1; cvt.u32.u64 %0, t; }"
        : "=r"(a) : "l"(p));
    return a;
}

__device__ __forceinline__ void cpa16(uint32_t dst, const void* src) {
    asm volatile("cp.async.cg.shared.global [%0], [%1], 16;" :: "r"(dst), "l"(src));
}

__device__ __forceinline__ void mma_f16(
    float& c0, float& c1, float& c2, float& c3,
    uint32_t a0, uint32_t a1, uint32_t a2, uint32_t a3,
    uint32_t b0, uint32_t b1)
{
    asm volatile(
        "mma.sync.aligned.m16n8k16.row.col.f32.f16.f16.f32 "
        "{%0,%1,%2,%3}, {%4,%5,%6,%7}, {%8,%9}, {%0,%1,%2,%3};"
        : "+f"(c0), "+f"(c1), "+f"(c2), "+f"(c3)
        : "r"(a0), "r"(a1), "r"(a2), "r"(a3), "r"(b0), "r"(b1));
}

// --------------------------- LayerNorm row body -----------------------------
__device__ __forceinline__ void ln_row(
    const float* __restrict__ in, const float* __restrict__ gamma,
    const float* __restrict__ beta, __half* __restrict__ out, int row)
{
    __shared__ float red[16];
    const int tid = threadIdx.x;
    const float* x = in + (size_t)row * DMODEL;

    float4 v = *(const float4*)(x + tid * 4);
    float s = v.x + v.y + v.z + v.w;
    float q = v.x * v.x + v.y * v.y + v.z * v.z + v.w * v.w;
    #pragma unroll
    for (int off = 16; off; off >>= 1) {
        s += __shfl_xor_sync(0xffffffffu, s, off);
        q += __shfl_xor_sync(0xffffffffu, q, off);
    }
    const int w = tid >> 5;
    if ((tid & 31) == 0) { red[w] = s; red[8 + w] = q; }
    __syncthreads();
    float st = 0.f, qt = 0.f;
    #pragma unroll
    for (int i = 0; i < 8; i++) { st += red[i]; qt += red[8 + i]; }

    const float mu  = st * (1.0f / DMODEL);
    const float var = qt * (1.0f / DMODEL) - mu * mu;
    const float inv = rsqrtf(var + EPS);

    float4 g = *(const float4*)(gamma + tid * 4);
    float4 b = *(const float4*)(beta  + tid * 4);
    __half2 p0 = __floats2half2_rn((v.x - mu) * inv * g.x + b.x,
                                   (v.y - mu) * inv * g.y + b.y);
    __half2 p1 = __floats2half2_rn((v.z - mu) * inv * g.z + b.z,
                                   (v.w - mu) * inv * g.w + b.w);
    uint2 pk;
    pk.x = *(uint32_t*)&p0;
    pk.y = *(uint32_t*)&p1;
    *(uint2*)(out + (size_t)row * DMODEL + tid * 4) = pk;
}

__global__ void __launch_bounds__(256) ln_kernel(
    const float* __restrict__ in, const float* __restrict__ gamma,
    const float* __restrict__ beta, __half* __restrict__ out)
{
    ln_row(in, gamma, beta, out, blockIdx.x);
}

// ---------------- fused prep: LN1 + 4 weight transposes ---------------------
// blocks [0, 4096): LN1 rows. blocks [4096, 16384): 32x32 transpose tiles.
__global__ void __launch_bounds__(256) prep_kernel(
    const float* __restrict__ hidden, const float* __restrict__ g1,
    const float* __restrict__ be1, __half* __restrict__ x,
    const float* __restrict__ w_qkv, const float* __restrict__ w_proj,
    const float* __restrict__ w_fc,  const float* __restrict__ w_mlp,
    __half* __restrict__ wT)
{
    const int bid = blockIdx.x;
    if (bid < ROWS) {
        ln_row(hidden, g1, be1, x, bid);
        return;
    }
    int t = bid - ROWS;
    const float* in;
    __half* outp;
    int K, N, bx, by;
    if (t < 3072)      { in = w_qkv;  outp = (__half*)wT + WT_QKV_OFF;
                         K = 1024; N = 3072; bx = t % 96;  by = t / 96; }
    else if (t < 4096) { t -= 3072; in = w_proj; outp = (__half*)wT + WT_PROJ_OFF;
                         K = 1024; N = 1024; bx = t % 32;  by = t / 32; }
    else if (t < 8192) { t -= 4096; in = w_fc;   outp = (__half*)wT + WT_FC_OFF;
                         K = 1024; N = 4096; bx = t % 128; by = t / 128; }
    else               { t -= 8192; in = w_mlp;  outp = (__half*)wT + WT_MLP_OFF;
                         K = 4096; N = 1024; bx = t % 32;  by = t / 32; }

    __shared__ float tt[32][33];
    const int n0 = bx * 32, k0 = by * 32;
    const int tx = threadIdx.x & 31;
    const int ty = threadIdx.x >> 5;
    #pragma unroll
    for (int i = 0; i < 32; i += 8)
        tt[ty + i][tx] = in[(size_t)(k0 + ty + i) * N + n0 + tx];
    __syncthreads();
    #pragma unroll
    for (int i = 0; i < 32; i += 8)
        outp[(size_t)(n0 + ty + i) * K + k0 + tx] = __float2half(tt[tx][ty + i]);
}

// ------------------------------ fp16 MMA GEMM -------------------------------
// C[M,N] = A[M,K] @ Bt[N,K]^T (+bias, +res | gelu). 128x128 CTA tile, BK=64,
// 8 warps (2Mx4N), warp tile 64x32, m16n8k16. 3-stage ring, 2 CTAs/SM.
#define EPI_QKV   0
#define EPI_RES   1
#define EPI_GELU  2

#define BKH      64
#define SPH      72
#define SPW      (SPH / 2)
#define TILE_H   (128 * SPH)
#define STAGE_H  (2 * TILE_H)
#define GSTAGES  3
#define GSMEM_DYN (GSTAGES * STAGE_H * 2)   // 110592 B -> 2 CTAs/SM

template <int EPI>
__global__ void __launch_bounds__(256, 2) hgemm_kernel(
    const __half* __restrict__ A, const __half* __restrict__ Bt,
    const float* __restrict__ bias, const float* __restrict__ res,
    void* __restrict__ Cv, __half* __restrict__ vT, int M, int N, int K)
{
    extern __shared__ __half smh[];

    const int tid   = threadIdx.x;
    const int wid   = tid >> 5;
    const int lane  = tid & 31;
    const int gi    = lane >> 2;
    const int tig   = lane & 3;
    const int warpM = wid >> 2;
    const int warpN = wid & 3;

    const int mrow0 = blockIdx.y * 128;
    const int ncol0 = blockIdx.x * 128;

    const __half* Abase = A  + (size_t)mrow0 * K;
    const __half* Bbase = Bt + (size_t)ncol0 * K;

    const uint32_t smem_base = smem_u32(smh);

    float acc[4][4][4];
    #pragma unroll
    for (int i = 0; i < 4; i++)
        #pragma unroll
        for (int j = 0; j < 4; j++)
            #pragma unroll
            for (int q = 0; q < 4; q++) acc[i][j][q] = 0.f;

    const int NC = K / BKH;

    auto load_stage = [&](int c) {
        const int s = c % GSTAGES;
        const uint32_t a_st = smem_base + s * STAGE_H * 2;
        const uint32_t b_st = a_st + TILE_H * 2;
        const int kof = c * BKH;
        #pragma unroll
        for (int i = 0; i < 4; i++) {
            const int lin = tid + i * 256;
            const int r   = lin >> 3;
            const int cc  = lin & 7;
            const uint32_t off = (uint32_t)(r * (SPH * 2) + cc * 16);
            cpa16(a_st + off, Abase + (size_t)r * K + kof + cc * 8);
            cpa16(b_st + off, Bbase + (size_t)r * K + kof + cc * 8);
        }
    };

    #pragma unroll
    for (int p = 0; p < GSTAGES - 1; p++) {
        load_stage(p);
        asm volatile("cp.async.commit_group;" ::: "memory");
    }

    for (int c = 0; c < NC; c++) {
        asm volatile("cp.async.wait_group %0;" :: "n"(GSTAGES - 2) : "memory");
        __syncthreads();

        if (c + GSTAGES - 1 < NC) load_stage(c + GSTAGES - 1);
        asm volatile("cp.async.commit_group;" ::: "memory");

        const uint32_t* As32 = (const uint32_t*)(smh + (c % GSTAGES) * STAGE_H);
        const uint32_t* Bs32 = As32 + TILE_H / 2;
        const uint32_t* Aw = As32 + (warpM * 64 + gi) * SPW + tig;
        const uint32_t* Bw = Bs32 + (warpN * 32 + gi) * SPW + tig;

        #pragma unroll
        for (int ks = 0; ks < 4; ks++) {
            uint32_t af[4][4], bf[4][2];
            #pragma unroll
            for (int im = 0; im < 4; im++) {
                const uint32_t* p = Aw + im * 16 * SPW + ks * 8;
                af[im][0] = p[0];
                af[im][1] = p[8 * SPW];
                af[im][2] = p[4];
                af[im][3] = p[8 * SPW + 4];
            }
            #pragma unroll
            for (int jn = 0; jn < 4; jn++) {
                const uint32_t* p = Bw + jn * 8 * SPW + ks * 8;
                bf[jn][0] = p[0];
                bf[jn][1] = p[4];
            }
            #pragma unroll
            for (int im = 0; im < 4; im++)
                #pragma unroll
                for (int jn = 0; jn < 4; jn++)
                    mma_f16(acc[im][jn][0], acc[im][jn][1],
                            acc[im][jn][2], acc[im][jn][3],
                            af[im][0], af[im][1], af[im][2], af[im][3],
                            bf[jn][0], bf[jn][1]);
        }
    }

    // ---- epilogue ----------------------------------------------------------
    const bool vpart = (EPI == EPI_QKV) && (ncol0 >= 2 * DMODEL);
    #pragma unroll
    for (int im = 0; im < 4; im++) {
        const int r0 = mrow0 + warpM * 64 + im * 16 + gi;
        #pragma unroll
        for (int hf = 0; hf < 2; hf++) {
            const size_t row = (size_t)(r0 + hf * 8);
            #pragma unroll
            for (int jn = 0; jn < 4; jn++) {
                const int col = ncol0 + warpN * 32 + jn * 8 + tig * 2;
                float ox = acc[im][jn][hf * 2 + 0];
                float oy = acc[im][jn][hf * 2 + 1];
                float2 bv = *(const float2*)(bias + col);
                ox += bv.x; oy += bv.y;
                if (EPI == EPI_RES) {
                    float2 rv = *(const float2*)(res + row * N + col);
                    float2 o2 = {ox + rv.x, oy + rv.y};
                    *(float2*)((float*)Cv + row * N + col) = o2;
                } else if (EPI == EPI_GELU) {
                    __half2 hv = __floats2half2_rn(gelu_exact(ox), gelu_exact(oy));
                    *(__half2*)((__half*)Cv + row * N + col) = hv;
                } else {  // EPI_QKV
                    if (vpart) {
                        const int vcol = col - 2 * DMODEL;
                        const int hh = vcol >> 6, d = vcol & 63;
                        const int bb = (int)(row >> 11), tok = (int)(row & 2047);
                        __half* vp = vT +
                            ((size_t)((bb * NHEADS + hh) * HDIM + d)) * SEQ + tok;
                        vp[0]   = __float2half(ox);
                        vp[SEQ] = __float2half(oy);
                    } else {
                        __half2 hv = __floats2half2_rn(ox, oy);
                        *(__half2*)((__half*)Cv + row * N + col) = hv;
                    }
                }
            }
        }
    }
}

// ------------------------- Flash attention (fp16 MMA) -----------------------
#define KVH    (64 * SPH)
#define P_OFF  (4 * KVH)
#define ATTN_SMEM_B ((4 * KVH + 128 * SPH) * 2)   // 55296 B

__global__ void __launch_bounds__(256, 2) attn_kernel(
    const __half* __restrict__ qkv, const __half* __restrict__ vT,
    __half* __restrict__ out)
{
    extern __shared__ __half smh[];
    const uint32_t smem_base = smem_u32(smh);

    const int qt  = blockIdx.x;
    const int b   = blockIdx.y >> 4;
    const int h   = blockIdx.y & 15;
    const int tid = threadIdx.x;
    const int wid = tid >> 5;
    const int lane = tid & 31;
    const int gi  = lane >> 2;
    const int tig = lane & 3;

    const int q0 = qt * 128;
    const int qrow_w = q0 + wid * 16;
    const int nkt = qt * 2 + 2;

    auto load_tile = [&](int kt) {
        const int st = kt & 1;
        const __half* Kg = qkv + ((size_t)(b * SEQ + kt * 64)) * 3072
                           + DMODEL + h * HDIM;
        const __half* Vg = vT + ((size_t)((b * NHEADS + h) * HDIM)) * SEQ + kt * 64;
        const uint32_t Kd = smem_base + st * (KVH * 2);
        const uint32_t Vd = smem_base + (2 + st) * (KVH * 2);
        #pragma unroll
        for (int i = 0; i < 4; i++) {
            const int idx = tid + i * 256;
            if (idx < 512) {
                const int r = idx >> 3, cc = idx & 7;
                cpa16(Kd + r * (SPH * 2) + cc * 16, Kg + (size_t)r * 3072 + cc * 8);
            } else {
                const int j = idx - 512;
                const int r = j >> 3, cc = j & 7;
                cpa16(Vd + r * (SPH * 2) + cc * 16, Vg + (size_t)r * SEQ + cc * 8);
            }
        }
    };

    {
        const __half* Qg = qkv + ((size_t)(b * SEQ + q0)) * 3072 + h * HDIM;
        const uint32_t Pd = smem_base + P_OFF * 2;
        #pragma unroll
        for (int i = 0; i < 4; i++) {
            const int idx = tid + i * 256;
            const int r = idx >> 3, cc = idx & 7;
            cpa16(Pd + r * (SPH * 2) + cc * 16, Qg + (size_t)r * 3072 + cc * 8);
        }
        asm volatile("cp.async.commit_group;" ::: "memory");
        load_tile(0);
        asm volatile("cp.async.commit_group;" ::: "memory");
        asm volatile("cp.async.wait_group 0;" ::: "memory");
        __syncthreads();
    }

    uint32_t qf[4][4];
    const uint32_t* Pw32 = (const uint32_t*)(smh + P_OFF)
                           + (wid * 16 + gi) * SPW + tig;
    #pragma unroll
    for (int ks = 0; ks < 4; ks++) {
        qf[ks][0] = Pw32[ks * 8];
        qf[ks][1] = Pw32[8 * SPW + ks * 8];
        qf[ks][2] = Pw32[ks * 8 + 4];
        qf[ks][3] = Pw32[8 * SPW + ks * 8 + 4];
    }

    float m[2] = {-1e30f, -1e30f};
    float l[2] = {0.f, 0.f};
    float o[8][4];
    #pragma unroll
    for (int jn = 0; jn < 8; jn++)
        #pragma unroll
        for (int q = 0; q < 4; q++) o[jn][q] = 0.f;

    for (int kt = 0; kt < nkt; kt++) {
        if (kt > 0) {
            asm volatile("cp.async.wait_group 0;" ::: "memory");
            __syncthreads();
        }
        if (kt + 1 < nkt) {
            load_tile(kt + 1);
            asm volatile("cp.async.commit_group;" ::: "memory");
        }

        const int st = kt & 1;
        const uint32_t* Ks32 = (const uint32_t*)(smh + st * KVH);
        const uint32_t* Vs32 = (const uint32_t*)(smh + (2 + st) * KVH);

        float s[8][4];
        #pragma unroll
        for (int jn = 0; jn < 8; jn++)
            #pragma unroll
            for (int q = 0; q < 4; q++) s[jn][q] = 0.f;

        #pragma unroll
        for (int ks = 0; ks < 4; ks++) {
            #pragma unroll
            for (int jn = 0; jn < 8; jn++) {
                const uint32_t* kp = Ks32 + (jn * 8 + gi) * SPW + ks * 8 + tig;
                mma_f16(s[jn][0], s[jn][1], s[jn][2], s[jn][3],
                        qf[ks][0], qf[ks][1], qf[ks][2], qf[ks][3],
                        kp[0], kp[4]);
            }
        }

        #pragma unroll
        for (int jn = 0; jn < 8; jn++)
            #pragma unroll
            for (int q = 0; q < 4; q++) s[jn][q] *= 0.125f;

        if (kt * 64 + 63 > qrow_w) {
            #pragma unroll
            for (int jn = 0; jn < 8; jn++) {
                const int kc = kt * 64 + jn * 8 + tig * 2;
                const int r0 = qrow_w + gi;
                const int r1 = r0 + 8;
                if (kc     > r0) s[jn][0] = -1e30f;
                if (kc + 1 > r0) s[jn][1] = -1e30f;
                if (kc     > r1) s[jn][2] = -1e30f;
                if (kc + 1 > r1) s[jn][3] = -1e30f;
            }
        }

        #pragma unroll
        for (int rr = 0; rr < 2; rr++) {
            const int i0 = rr * 2, i1 = rr * 2 + 1;
            float mx = -1e30f;
            #pragma unroll
            for (int jn = 0; jn < 8; jn++)
                mx = fmaxf(mx, fmaxf(s[jn][i0], s[jn][i1]));
            mx = fmaxf(mx, __shfl_xor_sync(0xffffffffu, mx, 1));
            mx = fmaxf(mx, __shfl_xor_sync(0xffffffffu, mx, 2));
            const float mn = fmaxf(m[rr], mx);
            const float al = __expf(m[rr] - mn);
            float rs = 0.f;
            #pragma unroll
            for (int jn = 0; jn < 8; jn++) {
                const float e0 = __expf(s[jn][i0] - mn);
                const float e1 = __expf(s[jn][i1] - mn);
                s[jn][i0] = e0; s[jn][i1] = e1;
                rs += e0 + e1;
            }
            rs += __shfl_xor_sync(0xffffffffu, rs, 1);
            rs += __shfl_xor_sync(0xffffffffu, rs, 2);
            l[rr] = l[rr] * al + rs;
            m[rr] = mn;
            #pragma unroll
            for (int jn = 0; jn < 8; jn++) { o[jn][i0] *= al; o[jn][i1] *= al; }
        }

        {
            uint32_t* Pst = (uint32_t*)(smh + P_OFF) + (wid * 16 + gi) * SPW;
            #pragma unroll
            for (int jn = 0; jn < 8; jn++) {
                __half2 p0 = __floats2half2_rn(s[jn][0], s[jn][1]);
                __half2 p1 = __floats2half2_rn(s[jn][2], s[jn][3]);
                Pst[jn * 4 + tig]           = *(uint32_t*)&p0;
                Pst[8 * SPW + jn * 4 + tig] = *(uint32_t*)&p1;
            }
        }
        __syncwarp();

        #pragma unroll
        for (int ks = 0; ks < 4; ks++) {
            const uint32_t a0 = Pw32[ks * 8];
            const uint32_t a1 = Pw32[8 * SPW + ks * 8];
            const uint32_t a2 = Pw32[ks * 8 + 4];
            const uint32_t a3 = Pw32[8 * SPW + ks * 8 + 4];
            #pragma unroll
            for (int jn = 0; jn < 8; jn++) {
                const uint32_t* vp = Vs32 + (jn * 8 + gi) * SPW + ks * 8 + tig;
                mma_f16(o[jn][0], o[jn][1], o[jn][2], o[jn][3],
                        a0, a1, a2, a3, vp[0], vp[4]);
            }
        }
        __syncwarp();
    }

    const float inv0 = 1.0f / l[0];
    const float inv1 = 1.0f / l[1];
    __half* O0 = out + ((size_t)(b * SEQ) + qrow_w + gi)     * DMODEL + h * HDIM;
    __half* O1 = out + ((size_t)(b * SEQ) + qrow_w + gi + 8) * DMODEL + h * HDIM;
    #pragma unroll
    for (int jn = 0; jn < 8; jn++) {
        __half2 v0 = __floats2half2_rn(o[jn][0] * inv0, o[jn][1] * inv0);
        __half2 v1 = __floats2half2_rn(o[jn][2] * inv1, o[jn][3] * inv1);
        *(__half2*)(O0 + jn * 8 + tig * 2) = v0;
        *(__half2*)(O1 + jn * 8 + tig * 2) = v1;
    }
}

// ------------------------------- launcher -----------------------------------
extern "C" void kernel_launch(void* const* d_in, const int* in_sizes, int n_in,
                              void* d_out, int out_size)
{
    const float* hidden = (const float*)d_in[0];
    const float* w_qkv  = (const float*)d_in[1];
    const float* b_qkv  = (const float*)d_in[2];
    const float* g1     = (const float*)d_in[3];
    const float* be1    = (const float*)d_in[4];
    const float* w_proj = (const float*)d_in[5];
    const float* b_proj = (const float*)d_in[6];
    const float* g2     = (const float*)d_in[7];
    const float* be2    = (const float*)d_in[8];
    const float* w_fc   = (const float*)d_in[9];
    const float* b_fc   = (const float*)d_in[10];
    const float* w_mlp  = (const float*)d_in[11];
    const float* b_mlp  = (const float*)d_in[12];
    float* out = (float*)d_out;

    __half *x, *qkv, *vT, *attn, *y, *fc, *wT;
    float  *h2;
    cudaGetSymbolAddress((void**)&x,    g_x);
    cudaGetSymbolAddress((void**)&qkv,  g_qkv);
    cudaGetSymbolAddress((void**)&vT,   g_vT);
    cudaGetSymbolAddress((void**)&attn, g_attn);
    cudaGetSymbolAddress((void**)&h2,   g_h2);
    cudaGetSymbolAddress((void**)&y,    g_y);
    cudaGetSymbolAddress((void**)&fc,   g_fc);
    cudaGetSymbolAddress((void**)&wT,   g_wT);

    __half* wT_qkv  = wT + WT_QKV_OFF;
    __half* wT_proj = wT + WT_PROJ_OFF;
    __half* wT_fc   = wT + WT_FC_OFF;
    __half* wT_mlp  = wT + WT_MLP_OFF;

    cudaFuncSetAttribute(attn_kernel,
                         cudaFuncAttributeMaxDynamicSharedMemorySize, ATTN_SMEM_B);
    cudaFuncSetAttribute(hgemm_kernel<EPI_QKV>,
                         cudaFuncAttributeMaxDynamicSharedMemorySize, GSMEM_DYN);
    cudaFuncSetAttribute(hgemm_kernel<EPI_RES>,
                         cudaFuncAttributeMaxDynamicSharedMemorySize, GSMEM_DYN);
    cudaFuncSetAttribute(hgemm_kernel<EPI_GELU>,
                         cudaFuncAttributeMaxDynamicSharedMemorySize, GSMEM_DYN);

    // 1. prep: LN1 + all 4 weight transposes in one launch
    prep_kernel<<<ROWS + 12288, 256>>>(hidden, g1, be1, x,
                                       w_qkv, w_proj, w_fc, w_mlp, wT);
    // 2. QKV (Q,K -> qkv half; V -> vT transposed)
    hgemm_kernel<EPI_QKV><<<dim3(3 * DMODEL / 128, ROWS / 128), 256, GSMEM_DYN>>>(
        x, wT_qkv, b_qkv, nullptr, qkv, vT, ROWS, 3 * DMODEL, DMODEL);
    // 3. attention -> half
    attn_kernel<<<dim3(SEQ / 128, BATCH * NHEADS), 256, ATTN_SMEM_B>>>(qkv, vT, attn);
    // 4. h2 = attn @ w_proj + b_proj + hidden  (f32)
    hgemm_kernel<EPI_RES><<<dim3(DMODEL / 128, ROWS / 128), 256, GSMEM_DYN>>>(
        attn, wT_proj, b_proj, hidden, h2, nullptr, ROWS, DMODEL, DMODEL);
    // 5. LN2 -> half
    ln_kernel<<<ROWS, 256>>>(h2, g2, be2, y);
    // 6. fc = gelu(y @ w_fc + b_fc) -> half
    hgemm_kernel<EPI_GELU><<<dim3(INNER / 128, ROWS / 128), 256, GSMEM_DYN>>>(
        y, wT_fc, b_fc, nullptr, fc, nullptr, ROWS, INNER, DMODEL);
    // 7. out = fc @ w_mlp + b_mlp + h2  (f32)
    hgemm_kernel<EPI_RES><<<dim3(DMODEL / 128, ROWS / 128), 256, GSMEM_DYN>>>(
        fc, wT_mlp, b_mlp, h2, out, nullptr, ROWS, DMODEL, INNER);
}

// round 10
// speedup vs baseline: 6.6447x; 1.0665x over previous
#include <cuda_runtime.h>
#include <cuda_fp16.h>
#include <math.h>
#include <stdint.h>

// ---------------------------------------------------------------------------
// GPT-2 block, fp16 mma.sync (m16n8k16) + ldmatrix fragment loads.
// B=2, S=2048, D=1024, H=16, dh=64, INNER=4096
// ---------------------------------------------------------------------------

#define BATCH   2
#define SEQ     2048
#define DMODEL  1024
#define NHEADS  16
#define HDIM    64
#define INNER   4096
#define ROWS    (BATCH * SEQ)
#define EPS     1e-5f

// ------------------------- scratch (static device mem) ---------------------
__device__ __half g_x   [ROWS * DMODEL];
__device__ __half g_qkv [ROWS * 3 * DMODEL];
__device__ __half g_vT  [BATCH * NHEADS * HDIM * SEQ];
__device__ __half g_attn[ROWS * DMODEL];
__device__ float  g_h2  [ROWS * DMODEL];
__device__ __half g_y   [ROWS * DMODEL];
__device__ __half g_fc  [ROWS * INNER];
__device__ __half g_wT  [12 * 1024 * 1024];
#define WT_QKV_OFF  0
#define WT_PROJ_OFF (3072 * 1024)
#define WT_FC_OFF   (WT_PROJ_OFF + 1024 * 1024)
#define WT_MLP_OFF  (WT_FC_OFF + 4096 * 1024)

// ------------------------------ small helpers -------------------------------
__device__ __forceinline__ float gelu_exact(float x) {
    return 0.5f * x * (1.0f + erff(x * 0.70710678118654752f));
}

__device__ __forceinline__ uint32_t smem_u32(const void* p) {
    uint32_t a;
    asm("{ .reg .u64 t; cvta.to.shared.u64 t, %1; cvt.u32.u64 %0, t; }"
        : "=r"(a) : "l"(p));
    return a;
}

__device__ __forceinline__ void cpa16(uint32_t dst, const void* src) {
    asm volatile("cp.async.cg.shared.global [%0], [%1], 16;" :: "r"(dst), "l"(src));
}

__device__ __forceinline__ void mma_f16(
    float& c0, float& c1, float& c2, float& c3,
    uint32_t a0, uint32_t a1, uint32_t a2, uint32_t a3,
    uint32_t b0, uint32_t b1)
{
    asm volatile(
        "mma.sync.aligned.m16n8k16.row.col.f32.f16.f16.f32 "
        "{%0,%1,%2,%3}, {%4,%5,%6,%7}, {%8,%9}, {%0,%1,%2,%3};"
        : "+f"(c0), "+f"(c1), "+f"(c2), "+f"(c3)
        : "r"(a0), "r"(a1), "r"(a2), "r"(a3), "r"(b0), "r"(b1));
}

// ldmatrix x4, non-transposed. Lane l supplies the address of a 16B row:
// lanes 0-7 -> matrix0, 8-15 -> matrix1, 16-23 -> matrix2, 24-31 -> matrix3.
__device__ __forceinline__ void ldsm4(
    uint32_t& r0, uint32_t& r1, uint32_t& r2, uint32_t& r3, uint32_t addr)
{
    asm volatile(
        "ldmatrix.sync.aligned.m8n8.x4.shared.b16 {%0,%1,%2,%3}, [%4];"
        : "=r"(r0), "=r"(r1), "=r"(r2), "=r"(r3) : "r"(addr));
}

// --------------------------- LayerNorm row body -----------------------------
__device__ __forceinline__ void ln_row(
    const float* __restrict__ in, const float* __restrict__ gamma,
    const float* __restrict__ beta, __half* __restrict__ out, int row)
{
    __shared__ float red[16];
    const int tid = threadIdx.x;
    const float* x = in + (size_t)row * DMODEL;

    float4 v = *(const float4*)(x + tid * 4);
    float s = v.x + v.y + v.z + v.w;
    float q = v.x * v.x + v.y * v.y + v.z * v.z + v.w * v.w;
    #pragma unroll
    for (int off = 16; off; off >>= 1) {
        s += __shfl_xor_sync(0xffffffffu, s, off);
        q += __shfl_xor_sync(0xffffffffu, q, off);
    }
    const int w = tid >> 5;
    if ((tid & 31) == 0) { red[w] = s; red[8 + w] = q; }
    __syncthreads();
    float st = 0.f, qt = 0.f;
    #pragma unroll
    for (int i = 0; i < 8; i++) { st += red[i]; qt += red[8 + i]; }

    const float mu  = st * (1.0f / DMODEL);
    const float var = qt * (1.0f / DMODEL) - mu * mu;
    const float inv = rsqrtf(var + EPS);

    float4 g = *(const float4*)(gamma + tid * 4);
    float4 b = *(const float4*)(beta  + tid * 4);
    __half2 p0 = __floats2half2_rn((v.x - mu) * inv * g.x + b.x,
                                   (v.y - mu) * inv * g.y + b.y);
    __half2 p1 = __floats2half2_rn((v.z - mu) * inv * g.z + b.z,
                                   (v.w - mu) * inv * g.w + b.w);
    uint2 pk;
    pk.x = *(uint32_t*)&p0;
    pk.y = *(uint32_t*)&p1;
    *(uint2*)(out + (size_t)row * DMODEL + tid * 4) = pk;
}

__global__ void __launch_bounds__(256) ln_kernel(
    const float* __restrict__ in, const float* __restrict__ gamma,
    const float* __restrict__ beta, __half* __restrict__ out)
{
    ln_row(in, gamma, beta, out, blockIdx.x);
}

// ---------------- fused prep: LN1 + 4 weight transposes ---------------------
__global__ void __launch_bounds__(256) prep_kernel(
    const float* __restrict__ hidden, const float* __restrict__ g1,
    const float* __restrict__ be1, __half* __restrict__ x,
    const float* __restrict__ w_qkv, const float* __restrict__ w_proj,
    const float* __restrict__ w_fc,  const float* __restrict__ w_mlp,
    __half* __restrict__ wT)
{
    const int bid = blockIdx.x;
    if (bid < ROWS) {
        ln_row(hidden, g1, be1, x, bid);
        return;
    }
    int t = bid - ROWS;
    const float* in;
    __half* outp;
    int K, N, bx, by;
    if (t < 3072)      { in = w_qkv;  outp = (__half*)wT + WT_QKV_OFF;
                         K = 1024; N = 3072; bx = t % 96;  by = t / 96; }
    else if (t < 4096) { t -= 3072; in = w_proj; outp = (__half*)wT + WT_PROJ_OFF;
                         K = 1024; N = 1024; bx = t % 32;  by = t / 32; }
    else if (t < 8192) { t -= 4096; in = w_fc;   outp = (__half*)wT + WT_FC_OFF;
                         K = 1024; N = 4096; bx = t % 128; by = t / 128; }
    else               { t -= 8192; in = w_mlp;  outp = (__half*)wT + WT_MLP_OFF;
                         K = 4096; N = 1024; bx = t % 32;  by = t / 32; }

    __shared__ float tt[32][33];
    const int n0 = bx * 32, k0 = by * 32;
    const int tx = threadIdx.x & 31;
    const int ty = threadIdx.x >> 5;
    #pragma unroll
    for (int i = 0; i < 32; i += 8)
        tt[ty + i][tx] = in[(size_t)(k0 + ty + i) * N + n0 + tx];
    __syncthreads();
    #pragma unroll
    for (int i = 0; i < 32; i += 8)
        outp[(size_t)(n0 + ty + i) * K + k0 + tx] = __float2half(tt[tx][ty + i]);
}

// ------------------------------ fp16 MMA GEMM -------------------------------
// C[M,N] = A[M,K] @ Bt[N,K]^T (+bias, +res | gelu). 128x128 CTA tile, BK=64,
// 8 warps (2Mx4N), warp tile 64x32. 3-stage ring, 2 CTAs/SM, ldmatrix loads.
#define EPI_QKV   0
#define EPI_RES   1
#define EPI_GELU  2

#define BKH      64
#define SPH      72
#define SPW      (SPH / 2)
#define TILE_H   (128 * SPH)
#define STAGE_H  (2 * TILE_H)
#define GSTAGES  3
#define GSMEM_DYN (GSTAGES * STAGE_H * 2)   // 110592 B -> 2 CTAs/SM

template <int EPI>
__global__ void __launch_bounds__(256, 2) hgemm_kernel(
    const __half* __restrict__ A, const __half* __restrict__ Bt,
    const float* __restrict__ bias, const float* __restrict__ res,
    void* __restrict__ Cv, __half* __restrict__ vT, int M, int N, int K)
{
    extern __shared__ __half smh[];

    const int tid   = threadIdx.x;
    const int wid   = tid >> 5;
    const int lane  = tid & 31;
    const int gi    = lane >> 2;
    const int tig   = lane & 3;
    const int warpM = wid >> 2;
    const int warpN = wid & 3;

    const int mrow0 = blockIdx.y * 128;
    const int ncol0 = blockIdx.x * 128;

    const __half* Abase = A  + (size_t)mrow0 * K;
    const __half* Bbase = Bt + (size_t)ncol0 * K;

    const uint32_t smem_base = smem_u32(smh);

    // per-lane ldmatrix row/k offsets (bytes, relative to tile start)
    const uint32_t aOff = (uint32_t)(
        (warpM * 64 + (lane & 7) + (((lane >> 3) & 1) << 3)) * SPH
        + ((lane >> 4) << 3)) * 2;
    const uint32_t bOff = (uint32_t)(
        (warpN * 32 + (lane & 7) + ((lane >> 4) << 3)) * SPH
        + (((lane >> 3) & 1) << 3)) * 2;

    float acc[4][4][4];
    #pragma unroll
    for (int i = 0; i < 4; i++)
        #pragma unroll
        for (int j = 0; j < 4; j++)
            #pragma unroll
            for (int q = 0; q < 4; q++) acc[i][j][q] = 0.f;

    const int NC = K / BKH;

    auto load_stage = [&](int c) {
        const int s = c % GSTAGES;
        const uint32_t a_st = smem_base + s * STAGE_H * 2;
        const uint32_t b_st = a_st + TILE_H * 2;
        const int kof = c * BKH;
        #pragma unroll
        for (int i = 0; i < 4; i++) {
            const int lin = tid + i * 256;
            const int r   = lin >> 3;
            const int cc  = lin & 7;
            const uint32_t off = (uint32_t)(r * (SPH * 2) + cc * 16);
            cpa16(a_st + off, Abase + (size_t)r * K + kof + cc * 8);
            cpa16(b_st + off, Bbase + (size_t)r * K + kof + cc * 8);
        }
    };

    #pragma unroll
    for (int p = 0; p < GSTAGES - 1; p++) {
        load_stage(p);
        asm volatile("cp.async.commit_group;" ::: "memory");
    }

    for (int c = 0; c < NC; c++) {
        asm volatile("cp.async.wait_group %0;" :: "n"(GSTAGES - 2) : "memory");
        __syncthreads();

        if (c + GSTAGES - 1 < NC) load_stage(c + GSTAGES - 1);
        asm volatile("cp.async.commit_group;" ::: "memory");

        const uint32_t stage_base = smem_base + (c % GSTAGES) * STAGE_H * 2;
        const uint32_t aAddr = stage_base + aOff;
        const uint32_t bAddr = stage_base + TILE_H * 2 + bOff;

        #pragma unroll
        for (int ks = 0; ks < 4; ks++) {
            uint32_t af[4][4], bf[4][2];
            #pragma unroll
            for (int im = 0; im < 4; im++)
                ldsm4(af[im][0], af[im][1], af[im][2], af[im][3],
                      aAddr + im * (16 * SPH * 2) + ks * 32);
            ldsm4(bf[0][0], bf[0][1], bf[1][0], bf[1][1], bAddr + ks * 32);
            ldsm4(bf[2][0], bf[2][1], bf[3][0], bf[3][1],
                  bAddr + 16 * SPH * 2 + ks * 32);
            #pragma unroll
            for (int im = 0; im < 4; im++)
                #pragma unroll
                for (int jn = 0; jn < 4; jn++)
                    mma_f16(acc[im][jn][0], acc[im][jn][1],
                            acc[im][jn][2], acc[im][jn][3],
                            af[im][0], af[im][1], af[im][2], af[im][3],
                            bf[jn][0], bf[jn][1]);
        }
    }

    // ---- epilogue ----------------------------------------------------------
    const bool vpart = (EPI == EPI_QKV) && (ncol0 >= 2 * DMODEL);
    #pragma unroll
    for (int im = 0; im < 4; im++) {
        const int r0 = mrow0 + warpM * 64 + im * 16 + gi;
        #pragma unroll
        for (int hf = 0; hf < 2; hf++) {
            const size_t row = (size_t)(r0 + hf * 8);
            #pragma unroll
            for (int jn = 0; jn < 4; jn++) {
                const int col = ncol0 + warpN * 32 + jn * 8 + tig * 2;
                float ox = acc[im][jn][hf * 2 + 0];
                float oy = acc[im][jn][hf * 2 + 1];
                float2 bv = *(const float2*)(bias + col);
                ox += bv.x; oy += bv.y;
                if (EPI == EPI_RES) {
                    float2 rv = *(const float2*)(res + row * N + col);
                    float2 o2 = {ox + rv.x, oy + rv.y};
                    *(float2*)((float*)Cv + row * N + col) = o2;
                } else if (EPI == EPI_GELU) {
                    __half2 hv = __floats2half2_rn(gelu_exact(ox), gelu_exact(oy));
                    *(__half2*)((__half*)Cv + row * N + col) = hv;
                } else {  // EPI_QKV
                    if (vpart) {
                        const int vcol = col - 2 * DMODEL;
                        const int hh = vcol >> 6, d = vcol & 63;
                        const int bb = (int)(row >> 11), tok = (int)(row & 2047);
                        __half* vp = vT +
                            ((size_t)((bb * NHEADS + hh) * HDIM + d)) * SEQ + tok;
                        vp[0]   = __float2half(ox);
                        vp[SEQ] = __float2half(oy);
                    } else {
                        __half2 hv = __floats2half2_rn(ox, oy);
                        *(__half2*)((__half*)Cv + row * N + col) = hv;
                    }
                }
            }
        }
    }
}

// ------------------------- Flash attention (fp16 MMA) -----------------------
#define KVH    (64 * SPH)
#define P_OFF  (4 * KVH)
#define ATTN_SMEM_B ((4 * KVH + 128 * SPH) * 2)   // 55296 B

__global__ void __launch_bounds__(256, 2) attn_kernel(
    const __half* __restrict__ qkv, const __half* __restrict__ vT,
    __half* __restrict__ out)
{
    extern __shared__ __half smh[];
    const uint32_t smem_base = smem_u32(smh);

    const int qt  = blockIdx.x;
    const int b   = blockIdx.y >> 4;
    const int h   = blockIdx.y & 15;
    const int tid = threadIdx.x;
    const int wid = tid >> 5;
    const int lane = tid & 31;
    const int gi  = lane >> 2;
    const int tig = lane & 3;

    const int q0 = qt * 128;
    const int qrow_w = q0 + wid * 16;
    const int nkt = qt * 2 + 2;

    // per-lane ldmatrix offsets (bytes, relative to tile start)
    const uint32_t nkOff = (uint32_t)(          // B-operand tiles (K rows, V rows)
        ((lane & 7) + ((lane >> 4) << 3)) * SPH
        + (((lane >> 3) & 1) << 3)) * 2;
    const uint32_t pOff = (uint32_t)(           // A-operand tile (P rows)
        (wid * 16 + (lane & 7) + (((lane >> 3) & 1) << 3)) * SPH
        + ((lane >> 4) << 3)) * 2;

    auto load_tile = [&](int kt) {
        const int st = kt & 1;
        const __half* Kg = qkv + ((size_t)(b * SEQ + kt * 64)) * 3072
                           + DMODEL + h * HDIM;
        const __half* Vg = vT + ((size_t)((b * NHEADS + h) * HDIM)) * SEQ + kt * 64;
        const uint32_t Kd = smem_base + st * (KVH * 2);
        const uint32_t Vd = smem_base + (2 + st) * (KVH * 2);
        #pragma unroll
        for (int i = 0; i < 4; i++) {
            const int idx = tid + i * 256;
            if (idx < 512) {
                const int r = idx >> 3, cc = idx & 7;
                cpa16(Kd + r * (SPH * 2) + cc * 16, Kg + (size_t)r * 3072 + cc * 8);
            } else {
                const int j = idx - 512;
                const int r = j >> 3, cc = j & 7;
                cpa16(Vd + r * (SPH * 2) + cc * 16, Vg + (size_t)r * SEQ + cc * 8);
            }
        }
    };

    {
        const __half* Qg = qkv + ((size_t)(b * SEQ + q0)) * 3072 + h * HDIM;
        const uint32_t Pd = smem_base + P_OFF * 2;
        #pragma unroll
        for (int i = 0; i < 4; i++) {
            const int idx = tid + i * 256;
            const int r = idx >> 3, cc = idx & 7;
            cpa16(Pd + r * (SPH * 2) + cc * 16, Qg + (size_t)r * 3072 + cc * 8);
        }
        asm volatile("cp.async.commit_group;" ::: "memory");
        load_tile(0);
        asm volatile("cp.async.commit_group;" ::: "memory");
        asm volatile("cp.async.wait_group 0;" ::: "memory");
        __syncthreads();
    }

    // Q fragments via ldmatrix
    uint32_t qf[4][4];
    {
        const uint32_t qAddr = smem_base + P_OFF * 2 + pOff;
        #pragma unroll
        for (int ks = 0; ks < 4; ks++)
            ldsm4(qf[ks][0], qf[ks][1], qf[ks][2], qf[ks][3], qAddr + ks * 32);
    }

    float m[2] = {-1e30f, -1e30f};
    float l[2] = {0.f, 0.f};
    float o[8][4];
    #pragma unroll
    for (int jn = 0; jn < 8; jn++)
        #pragma unroll
        for (int q = 0; q < 4; q++) o[jn][q] = 0.f;

    for (int kt = 0; kt < nkt; kt++) {
        if (kt > 0) {
            asm volatile("cp.async.wait_group 0;" ::: "memory");
            __syncthreads();
        }
        if (kt + 1 < nkt) {
            load_tile(kt + 1);
            asm volatile("cp.async.commit_group;" ::: "memory");
        }

        const int st = kt & 1;
        const uint32_t kAddr = smem_base + st * (KVH * 2) + nkOff;
        const uint32_t vAddr = smem_base + (2 + st) * (KVH * 2) + nkOff;

        // ---- S = Q @ K^T ----
        float s[8][4];
        #pragma unroll
        for (int jn = 0; jn < 8; jn++)
            #pragma unroll
            for (int q = 0; q < 4; q++) s[jn][q] = 0.f;

        #pragma unroll
        for (int ks = 0; ks < 4; ks++) {
            uint32_t bf[8][2];
            #pragma unroll
            for (int jnp = 0; jnp < 4; jnp++)
                ldsm4(bf[2 * jnp][0], bf[2 * jnp][1],
                      bf[2 * jnp + 1][0], bf[2 * jnp + 1][1],
                      kAddr + jnp * (16 * SPH * 2) + ks * 32);
            #pragma unroll
            for (int jn = 0; jn < 8; jn++)
                mma_f16(s[jn][0], s[jn][1], s[jn][2], s[jn][3],
                        qf[ks][0], qf[ks][1], qf[ks][2], qf[ks][3],
                        bf[jn][0], bf[jn][1]);
        }

        #pragma unroll
        for (int jn = 0; jn < 8; jn++)
            #pragma unroll
            for (int q = 0; q < 4; q++) s[jn][q] *= 0.125f;

        if (kt * 64 + 63 > qrow_w) {
            #pragma unroll
            for (int jn = 0; jn < 8; jn++) {
                const int kc = kt * 64 + jn * 8 + tig * 2;
                const int r0 = qrow_w + gi;
                const int r1 = r0 + 8;
                if (kc     > r0) s[jn][0] = -1e30f;
                if (kc + 1 > r0) s[jn][1] = -1e30f;
                if (kc     > r1) s[jn][2] = -1e30f;
                if (kc + 1 > r1) s[jn][3] = -1e30f;
            }
        }

        #pragma unroll
        for (int rr = 0; rr < 2; rr++) {
            const int i0 = rr * 2, i1 = rr * 2 + 1;
            float mx = -1e30f;
            #pragma unroll
            for (int jn = 0; jn < 8; jn++)
                mx = fmaxf(mx, fmaxf(s[jn][i0], s[jn][i1]));
            mx = fmaxf(mx, __shfl_xor_sync(0xffffffffu, mx, 1));
            mx = fmaxf(mx, __shfl_xor_sync(0xffffffffu, mx, 2));
            const float mn = fmaxf(m[rr], mx);
            const float al = __expf(m[rr] - mn);
            float rs = 0.f;
            #pragma unroll
            for (int jn = 0; jn < 8; jn++) {
                const float e0 = __expf(s[jn][i0] - mn);
                const float e1 = __expf(s[jn][i1] - mn);
                s[jn][i0] = e0; s[jn][i1] = e1;
                rs += e0 + e1;
            }
            rs += __shfl_xor_sync(0xffffffffu, rs, 1);
            rs += __shfl_xor_sync(0xffffffffu, rs, 2);
            l[rr] = l[rr] * al + rs;
            m[rr] = mn;
            #pragma unroll
            for (int jn = 0; jn < 8; jn++) { o[jn][i0] *= al; o[jn][i1] *= al; }
        }

        // ---- P -> warp-private smem (half) ----
        {
            uint32_t* Pst = (uint32_t*)(smh + P_OFF) + (wid * 16 + gi) * SPW;
            #pragma unroll
            for (int jn = 0; jn < 8; jn++) {
                __half2 p0 = __floats2half2_rn(s[jn][0], s[jn][1]);
                __half2 p1 = __floats2half2_rn(s[jn][2], s[jn][3]);
                Pst[jn * 4 + tig]           = *(uint32_t*)&p0;
                Pst[8 * SPW + jn * 4 + tig] = *(uint32_t*)&p1;
            }
        }
        __syncwarp();

        // ---- O += P @ V  (V tile is [d][tok]) ----
        const uint32_t pAddr = smem_base + P_OFF * 2 + pOff;
        #pragma unroll
        for (int ks = 0; ks < 4; ks++) {
            uint32_t a0, a1, a2, a3;
            ldsm4(a0, a1, a2, a3, pAddr + ks * 32);
            uint32_t vf[8][2];
            #pragma unroll
            for (int jnp = 0; jnp < 4; jnp++)
                ldsm4(vf[2 * jnp][0], vf[2 * jnp][1],
                      vf[2 * jnp + 1][0], vf[2 * jnp + 1][1],
                      vAddr + jnp * (16 * SPH * 2) + ks * 32);
            #pragma unroll
            for (int jn = 0; jn < 8; jn++)
                mma_f16(o[jn][0], o[jn][1], o[jn][2], o[jn][3],
                        a0, a1, a2, a3, vf[jn][0], vf[jn][1]);
        }
        __syncwarp();
    }

    const float inv0 = 1.0f / l[0];
    const float inv1 = 1.0f / l[1];
    __half* O0 = out + ((size_t)(b * SEQ) + qrow_w + gi)     * DMODEL + h * HDIM;
    __half* O1 = out + ((size_t)(b * SEQ) + qrow_w + gi + 8) * DMODEL + h * HDIM;
    #pragma unroll
    for (int jn = 0; jn < 8; jn++) {
        __half2 v0 = __floats2half2_rn(o[jn][0] * inv0, o[jn][1] * inv0);
        __half2 v1 = __floats2half2_rn(o[jn][2] * inv1, o[jn][3] * inv1);
        *(__half2*)(O0 + jn * 8 + tig * 2) = v0;
        *(__half2*)(O1 + jn * 8 + tig * 2) = v1;
    }
}

// ------------------------------- launcher -----------------------------------
extern "C" void kernel_launch(void* const* d_in, const int* in_sizes, int n_in,
                              void* d_out, int out_size)
{
    const float* hidden = (const float*)d_in[0];
    const float* w_qkv  = (const float*)d_in[1];
    const float* b_qkv  = (const float*)d_in[2];
    const float* g1     = (const float*)d_in[3];
    const float* be1    = (const float*)d_in[4];
    const float* w_proj = (const float*)d_in[5];
    const float* b_proj = (const float*)d_in[6];
    const float* g2     = (const float*)d_in[7];
    const float* be2    = (const float*)d_in[8];
    const float* w_fc   = (const float*)d_in[9];
    const float* b_fc   = (const float*)d_in[10];
    const float* w_mlp  = (const float*)d_in[11];
    const float* b_mlp  = (const float*)d_in[12];
    float* out = (float*)d_out;

    __half *x, *qkv, *vT, *attn, *y, *fc, *wT;
    float  *h2;
    cudaGetSymbolAddress((void**)&x,    g_x);
    cudaGetSymbolAddress((void**)&qkv,  g_qkv);
    cudaGetSymbolAddress((void**)&vT,   g_vT);
    cudaGetSymbolAddress((void**)&attn, g_attn);
    cudaGetSymbolAddress((void**)&h2,   g_h2);
    cudaGetSymbolAddress((void**)&y,    g_y);
    cudaGetSymbolAddress((void**)&fc,   g_fc);
    cudaGetSymbolAddress((void**)&wT,   g_wT);

    __half* wT_qkv  = wT + WT_QKV_OFF;
    __half* wT_proj = wT + WT_PROJ_OFF;
    __half* wT_fc   = wT + WT_FC_OFF;
    __half* wT_mlp  = wT + WT_MLP_OFF;

    cudaFuncSetAttribute(attn_kernel,
                         cudaFuncAttributeMaxDynamicSharedMemorySize, ATTN_SMEM_B);
    cudaFuncSetAttribute(hgemm_kernel<EPI_QKV>,
                         cudaFuncAttributeMaxDynamicSharedMemorySize, GSMEM_DYN);
    cudaFuncSetAttribute(hgemm_kernel<EPI_RES>,
                         cudaFuncAttributeMaxDynamicSharedMemorySize, GSMEM_DYN);
    cudaFuncSetAttribute(hgemm_kernel<EPI_GELU>,
                         cudaFuncAttributeMaxDynamicSharedMemorySize, GSMEM_DYN);

    // 1. prep: LN1 + all 4 weight transposes in one launch
    prep_kernel<<<ROWS + 12288, 256>>>(hidden, g1, be1, x,
                                       w_qkv, w_proj, w_fc, w_mlp, wT);
    // 2. QKV (Q,K -> qkv half; V -> vT transposed)
    hgemm_kernel<EPI_QKV><<<dim3(3 * DMODEL / 128, ROWS / 128), 256, GSMEM_DYN>>>(
        x, wT_qkv, b_qkv, nullptr, qkv, vT, ROWS, 3 * DMODEL, DMODEL);
    // 3. attention -> half
    attn_kernel<<<dim3(SEQ / 128, BATCH * NHEADS), 256, ATTN_SMEM_B>>>(qkv, vT, attn);
    // 4. h2 = attn @ w_proj + b_proj + hidden  (f32)
    hgemm_kernel<EPI_RES><<<dim3(DMODEL / 128, ROWS / 128), 256, GSMEM_DYN>>>(
        attn, wT_proj, b_proj, hidden, h2, nullptr, ROWS, DMODEL, DMODEL);
    // 5. LN2 -> half
    ln_kernel<<<ROWS, 256>>>(h2, g2, be2, y);
    // 6. fc = gelu(y @ w_fc + b_fc) -> half
    hgemm_kernel<EPI_GELU><<<dim3(INNER / 128, ROWS / 128), 256, GSMEM_DYN>>>(
        y, wT_fc, b_fc, nullptr, fc, nullptr, ROWS, INNER, DMODEL);
    // 7. out = fc @ w_mlp + b_mlp + h2  (f32)
    hgemm_kernel<EPI_RES><<<dim3(DMODEL / 128, ROWS / 128), 256, GSMEM_DYN>>>(
        fc, wT_mlp, b_mlp, h2, out, nullptr, ROWS, DMODEL, INNER);
}